// round 1
// baseline (speedup 1.0000x reference)
#include <cuda_runtime.h>
#include <math_constants.h>

// Problem constants
#define BATCH 4
#define SEQ   2048
#define EMB   1024
#define KVH   4       // kv heads
#define QHN   16      // q heads
#define GRP   4       // groups = QHN/KVH
#define HD    64      // head dim
#define NPROJ 256     // KVH*HD
#define MROWS (BATCH*SEQ)   // 8192

// Scratch (device globals; no allocation allowed)
__device__ float g_Wqe[EMB * NPROJ];          // group-folded Wq: [e][h][d]
__device__ float g_Q[BATCH * KVH * SEQ * HD]; // [b][h][s][d], rope'd + pre-scaled? (no, scale in flash)
__device__ float g_K[BATCH * KVH * SEQ * HD];
__device__ float g_V[BATCH * KVH * SEQ * HD];
__device__ float g_O[BATCH * KVH * SEQ * HD]; // per-head attention output

// ---------------------------------------------------------------------------
// Kernel 1: fold Wq over groups: Wq_eff[e,h,d] = sum_g Wq[e, h*GRP+g, d]
// ---------------------------------------------------------------------------
__global__ void fold_wq_kernel(const float* __restrict__ Wq) {
    int i = blockIdx.x * blockDim.x + threadIdx.x;   // over E*256
    int e  = i >> 8;
    int hd = i & 255;
    int h  = hd >> 6;
    int d  = hd & 63;
    float s = 0.f;
#pragma unroll
    for (int g = 0; g < GRP; g++)
        s += Wq[e * (QHN * HD) + (h * GRP + g) * HD + d];
    g_Wqe[i] = s;
}

// ---------------------------------------------------------------------------
// Kernel 2: fused QKV projection GEMM + RoPE epilogue.
// C = A(M=8192 x K=1024) * W(1024 x 256), 3 matrices (Q uses q input, K/V use kv).
// Tile: BM=64, BN=64, BK=16, 256 threads, 4x4 microtile.
// Output layout: [b][h][s][d]. RoPE applied for Q and K (mat<2).
// ---------------------------------------------------------------------------
__global__ void proj_kernel(const float* __restrict__ q,
                            const float* __restrict__ kv,
                            const float* __restrict__ Wk,
                            const float* __restrict__ Wv) {
    __shared__ __align__(16) float As[16][64];   // [k][m] transposed
    __shared__ __align__(16) float Bs[16][64];   // [k][n]

    int mat = blockIdx.x >> 2;             // 0=Q, 1=K, 2=V
    int n0  = (blockIdx.x & 3) * 64;       // head offset (one head per 64-col tile)
    int m0  = blockIdx.y * 64;

    const float* A = (mat == 0) ? q : kv;
    const float* W = (mat == 0) ? g_Wqe : (mat == 1 ? Wk : Wv);
    float* Out = (mat == 0) ? g_Q : (mat == 1 ? g_K : g_V);

    int t  = threadIdx.x;
    int tx = t & 15, ty = t >> 4;
    int lm = t >> 2, lq = t & 3;           // A-load: row lm, float4 index lq

    float acc[4][4] = {};

    for (int k0 = 0; k0 < EMB; k0 += 16) {
        // load A tile transposed
        float4 av = *(const float4*)&A[(m0 + lm) * EMB + k0 + lq * 4];
        As[lq * 4 + 0][lm] = av.x;
        As[lq * 4 + 1][lm] = av.y;
        As[lq * 4 + 2][lm] = av.z;
        As[lq * 4 + 3][lm] = av.w;
        // load W tile
#pragma unroll
        for (int i = 0; i < 4; i++) {
            int lin = t + i * 256;
            Bs[lin >> 6][lin & 63] = W[(k0 + (lin >> 6)) * NPROJ + n0 + (lin & 63)];
        }
        __syncthreads();
#pragma unroll
        for (int kk = 0; kk < 16; kk++) {
            float4 a = *(const float4*)&As[kk][ty * 4];
            float4 b = *(const float4*)&Bs[kk][tx * 4];
            acc[0][0] += a.x * b.x; acc[0][1] += a.x * b.y; acc[0][2] += a.x * b.z; acc[0][3] += a.x * b.w;
            acc[1][0] += a.y * b.x; acc[1][1] += a.y * b.y; acc[1][2] += a.y * b.z; acc[1][3] += a.y * b.w;
            acc[2][0] += a.z * b.x; acc[2][1] += a.z * b.y; acc[2][2] += a.z * b.z; acc[2][3] += a.z * b.w;
            acc[3][0] += a.w * b.x; acc[3][1] += a.w * b.y; acc[3][2] += a.w * b.z; acc[3][3] += a.w * b.w;
        }
        __syncthreads();
    }

    int h = n0 >> 6;
#pragma unroll
    for (int i = 0; i < 4; i++) {
        int row = m0 + ty * 4 + i;
        int b   = row >> 11;        // / SEQ
        int s   = row & 2047;       // % SEQ
        float* dst = &Out[(((b * KVH + h) * SEQ) + s) * HD + tx * 4];
        if (mat < 2) {
            // RoPE: interleaved pairs (d even, d odd)
#pragma unroll
            for (int jp = 0; jp < 2; jp++) {
                int d0 = tx * 4 + jp * 2;
                float freq = powf(10000.0f, -(float)d0 * (1.0f / 64.0f));
                float ang  = (float)s * freq;
                float sn, cs;
                sincosf(ang, &sn, &cs);
                float x1 = acc[i][jp * 2 + 0];
                float x2 = acc[i][jp * 2 + 1];
                dst[jp * 2 + 0] = x1 * cs - x2 * sn;
                dst[jp * 2 + 1] = x1 * sn + x2 * cs;
            }
        } else {
            float4 v = make_float4(acc[i][0], acc[i][1], acc[i][2], acc[i][3]);
            *(float4*)dst = v;
        }
    }
}

// ---------------------------------------------------------------------------
// Kernel 3: flash attention per (b,h). 64-row Q tile per block, online softmax.
// 256 threads (16x16), 4x4 microtiles for both S=QK^T and O=PV.
// smem stride 68 (byte stride 272 = multiple of 16 -> float4 OK, banks spread).
// ---------------------------------------------------------------------------
#define FST 68
__global__ void flash_kernel() {
    extern __shared__ __align__(16) float sm[];
    float* Qs = sm;                 // [dd][qrow] transposed, scaled by 1/8
    float* Ks = sm + 64 * FST;      // [dd][kcol] transposed
    float* Vs = sm + 2 * 64 * FST;  // [krow][d]
    float* Ps = sm + 3 * 64 * FST;  // [kcol][qrow] transposed

    int t  = threadIdx.x;
    int tx = t & 15, ty = t >> 4;
    int bh   = blockIdx.y;
    long base = (long)bh * SEQ * HD;
    int q0   = blockIdx.x * 64;

    // Load Q tile transposed, fold in 1/sqrt(HD)=0.125 scale
#pragma unroll
    for (int i = 0; i < 4; i++) {
        int lin = t + i * 256;
        int r   = lin >> 4;
        int c4  = (lin & 15) * 4;
        float4 v = *(const float4*)&g_Q[base + (q0 + r) * HD + c4];
        Qs[(c4 + 0) * FST + r] = v.x * 0.125f;
        Qs[(c4 + 1) * FST + r] = v.y * 0.125f;
        Qs[(c4 + 2) * FST + r] = v.z * 0.125f;
        Qs[(c4 + 3) * FST + r] = v.w * 0.125f;
    }

    float m[4], l[4], o[4][4];
#pragma unroll
    for (int i = 0; i < 4; i++) {
        m[i] = -CUDART_INF_F;
        l[i] = 0.f;
#pragma unroll
        for (int j = 0; j < 4; j++) o[i][j] = 0.f;
    }
    __syncthreads();

    for (int kt = 0; kt < SEQ / 64; kt++) {
        int k0 = kt * 64;
        // load K (transposed) and V (direct)
#pragma unroll
        for (int i = 0; i < 4; i++) {
            int lin = t + i * 256;
            int r   = lin >> 4;
            int c4  = (lin & 15) * 4;
            float4 kvv = *(const float4*)&g_K[base + (k0 + r) * HD + c4];
            Ks[(c4 + 0) * FST + r] = kvv.x;
            Ks[(c4 + 1) * FST + r] = kvv.y;
            Ks[(c4 + 2) * FST + r] = kvv.z;
            Ks[(c4 + 3) * FST + r] = kvv.w;
            float4 vv = *(const float4*)&g_V[base + (k0 + r) * HD + c4];
            *(float4*)&Vs[r * FST + c4] = vv;
        }
        __syncthreads();

        // S = Q * K^T (already scaled)
        float sc[4][4] = {};
#pragma unroll
        for (int dd = 0; dd < 64; dd++) {
            float4 a = *(const float4*)&Qs[dd * FST + ty * 4];
            float4 b = *(const float4*)&Ks[dd * FST + tx * 4];
            sc[0][0] += a.x * b.x; sc[0][1] += a.x * b.y; sc[0][2] += a.x * b.z; sc[0][3] += a.x * b.w;
            sc[1][0] += a.y * b.x; sc[1][1] += a.y * b.y; sc[1][2] += a.y * b.z; sc[1][3] += a.y * b.w;
            sc[2][0] += a.z * b.x; sc[2][1] += a.z * b.y; sc[2][2] += a.z * b.z; sc[2][3] += a.z * b.w;
            sc[3][0] += a.w * b.x; sc[3][1] += a.w * b.y; sc[3][2] += a.w * b.z; sc[3][3] += a.w * b.w;
        }

        // online softmax (row reduce across the 16 tx lanes of each row)
#pragma unroll
        for (int i = 0; i < 4; i++) {
            float rm = fmaxf(fmaxf(sc[i][0], sc[i][1]), fmaxf(sc[i][2], sc[i][3]));
#pragma unroll
            for (int msk = 8; msk >= 1; msk >>= 1)
                rm = fmaxf(rm, __shfl_xor_sync(0xffffffffu, rm, msk, 16));
            float mn  = fmaxf(m[i], rm);
            float fac = __expf(m[i] - mn);
            float rs  = 0.f;
#pragma unroll
            for (int j = 0; j < 4; j++) {
                sc[i][j] = __expf(sc[i][j] - mn);
                rs += sc[i][j];
            }
#pragma unroll
            for (int msk = 8; msk >= 1; msk >>= 1)
                rs += __shfl_xor_sync(0xffffffffu, rs, msk, 16);
            l[i] = l[i] * fac + rs;
            m[i] = mn;
#pragma unroll
            for (int j = 0; j < 4; j++) o[i][j] *= fac;
        }

        // stash P transposed
#pragma unroll
        for (int i = 0; i < 4; i++)
#pragma unroll
            for (int j = 0; j < 4; j++)
                Ps[(tx * 4 + j) * FST + (ty * 4 + i)] = sc[i][j];
        __syncthreads();

        // O += P * V
#pragma unroll
        for (int kk = 0; kk < 64; kk++) {
            float4 p = *(const float4*)&Ps[kk * FST + ty * 4];
            float4 v = *(const float4*)&Vs[kk * FST + tx * 4];
            o[0][0] += p.x * v.x; o[0][1] += p.x * v.y; o[0][2] += p.x * v.z; o[0][3] += p.x * v.w;
            o[1][0] += p.y * v.x; o[1][1] += p.y * v.y; o[1][2] += p.y * v.z; o[1][3] += p.y * v.w;
            o[2][0] += p.z * v.x; o[2][1] += p.z * v.y; o[2][2] += p.z * v.z; o[2][3] += p.z * v.w;
            o[3][0] += p.w * v.x; o[3][1] += p.w * v.y; o[3][2] += p.w * v.z; o[3][3] += p.w * v.w;
        }
        __syncthreads();
    }

#pragma unroll
    for (int i = 0; i < 4; i++) {
        float inv = 1.0f / l[i];
        float4 v = make_float4(o[i][0] * inv, o[i][1] * inv, o[i][2] * inv, o[i][3] * inv);
        *(float4*)&g_O[base + (q0 + ty * 4 + i) * HD + tx * 4] = v;
    }
}

// ---------------------------------------------------------------------------
// Kernel 4: out = (mean_h g_O) @ Wo. 64 rows per block, Wo staged 256 cols at
// a time through smem.
// ---------------------------------------------------------------------------
__global__ void out_kernel(const float* __restrict__ Wo, float* __restrict__ out) {
    extern __shared__ __align__(16) float sm[];
    float* ctx = sm;             // [64][64]
    float* Wos = sm + 64 * 64;   // [64][256]
    int t = threadIdx.x;
    int row0 = blockIdx.x * 64;

    // ctx = mean over 4 heads
#pragma unroll
    for (int i = 0; i < 16; i++) {
        int lin = t + i * 256;
        int r = lin >> 6, d = lin & 63;
        int grow = row0 + r;
        int b = grow >> 11, s = grow & 2047;
        float acc = 0.f;
#pragma unroll
        for (int h = 0; h < KVH; h++)
            acc += g_O[(((b * KVH + h) * SEQ) + s) * HD + d];
        ctx[r * 64 + d] = acc * 0.25f;
    }

    for (int e0 = 0; e0 < EMB; e0 += 256) {
        __syncthreads();
#pragma unroll 8
        for (int i = 0; i < 64; i++)
            Wos[i * 256 + t] = Wo[i * EMB + e0 + t];
        __syncthreads();
        for (int r = 0; r < 64; r++) {
            float a0 = 0.f, a1 = 0.f, a2 = 0.f, a3 = 0.f;
#pragma unroll
            for (int dd = 0; dd < 64; dd += 4) {
                a0 += ctx[r * 64 + dd + 0] * Wos[(dd + 0) * 256 + t];
                a1 += ctx[r * 64 + dd + 1] * Wos[(dd + 1) * 256 + t];
                a2 += ctx[r * 64 + dd + 2] * Wos[(dd + 2) * 256 + t];
                a3 += ctx[r * 64 + dd + 3] * Wos[(dd + 3) * 256 + t];
            }
            out[(row0 + r) * EMB + e0 + t] = (a0 + a1) + (a2 + a3);
        }
    }
}

// ---------------------------------------------------------------------------
extern "C" void kernel_launch(void* const* d_in, const int* in_sizes, int n_in,
                              void* d_out, int out_size) {
    const float* q  = (const float*)d_in[0];
    const float* kv = (const float*)d_in[1];
    const float* Wq = (const float*)d_in[2];
    const float* Wk = (const float*)d_in[3];
    const float* Wv = (const float*)d_in[4];
    const float* Wo = (const float*)d_in[5];
    float* out = (float*)d_out;

    const int flash_smem = 4 * 64 * FST * 4;                 // 69632 B
    const int out_smem   = (64 * 64 + 64 * 256) * 4;         // 81920 B
    cudaFuncSetAttribute(flash_kernel, cudaFuncAttributeMaxDynamicSharedMemorySize, flash_smem);
    cudaFuncSetAttribute(out_kernel,   cudaFuncAttributeMaxDynamicSharedMemorySize, out_smem);

    fold_wq_kernel<<<(EMB * NPROJ) / 256, 256>>>(Wq);
    proj_kernel<<<dim3(12, MROWS / 64), 256>>>(q, kv, Wk, Wv);
    flash_kernel<<<dim3(SEQ / 64, BATCH * KVH), 256, flash_smem>>>();
    out_kernel<<<MROWS / 64, 256, out_smem>>>(Wo, out);
}

// round 3
// speedup vs baseline: 2.0514x; 2.0514x over previous
#include <cuda_runtime.h>
#include <cuda_bf16.h>
#include <math_constants.h>
#include <stdint.h>

#define BATCH 4
#define SEQ   2048
#define EMB   1024
#define KVH   4
#define QHN   16
#define GRP   4
#define HD    64
#define NPROJ 256
#define MROWS (BATCH*SEQ)

__device__ float g_Wqe[EMB * NPROJ];
__device__ float g_Q[BATCH*KVH*SEQ*HD];
__device__ float g_K[BATCH*KVH*SEQ*HD];
__device__ float g_V[BATCH*KVH*SEQ*HD];
__device__ float g_O[BATCH*KVH*SEQ*HD];

// ---- bf16 split helpers -----------------------------------------------------
__device__ __forceinline__ uint32_t pack_bf2(float x, float y) {
    __nv_bfloat162 h = __floats2bfloat162_rn(x, y);
    return *reinterpret_cast<uint32_t*>(&h);
}
// x,y -> hi pair (bf16 of x,y) and lo pair (bf16 of residuals)
__device__ __forceinline__ void split2(float x, float y, uint32_t& hi, uint32_t& lo) {
    __nv_bfloat162 h = __floats2bfloat162_rn(x, y);
    float2 hf = __bfloat1622float2(h);
    hi = *reinterpret_cast<uint32_t*>(&h);
    lo = pack_bf2(x - hf.x, y - hf.y);
}
// D += A*B  (m16n8k16 bf16, fp32 accum)
__device__ __forceinline__ void mma16(float c[4], const uint32_t a[4], const uint32_t b[2]) {
    asm volatile("mma.sync.aligned.m16n8k16.row.col.f32.bf16.bf16.f32 "
        "{%0,%1,%2,%3}, {%4,%5,%6,%7}, {%8,%9}, {%0,%1,%2,%3};\n"
        : "+f"(c[0]), "+f"(c[1]), "+f"(c[2]), "+f"(c[3])
        : "r"(a[0]), "r"(a[1]), "r"(a[2]), "r"(a[3]), "r"(b[0]), "r"(b[1]));
}

// ---------------------------------------------------------------------------
// Kernel 1: fold Wq over groups
// ---------------------------------------------------------------------------
__global__ void fold_wq_kernel(const float* __restrict__ Wq) {
    int i = blockIdx.x * blockDim.x + threadIdx.x;
    int e  = i >> 8;
    int hd = i & 255;
    int h  = hd >> 6;
    int d  = hd & 63;
    float s = 0.f;
#pragma unroll
    for (int g = 0; g < GRP; g++)
        s += Wq[e * (QHN * HD) + (h * GRP + g) * HD + d];
    g_Wqe[i] = s;
}

// ---------------------------------------------------------------------------
// Kernel 2: QKV projection (bf16x3 tensor) + RoPE epilogue.
// Block 128x128, K-tile 32, 8 warps (4x2), warp tile 32x64.
// A smem: [m][k2] stride 20;  B smem: [k2][n] stride 136. (k2 = K/2, packed pairs)
// ---------------------------------------------------------------------------
#define ALD2 20
#define BLD2 136
__global__ __launch_bounds__(256) void proj_kernel(const float* __restrict__ q,
                            const float* __restrict__ kv,
                            const float* __restrict__ Wk,
                            const float* __restrict__ Wv) {
    __shared__ uint32_t As_hi[128*ALD2], As_lo[128*ALD2];
    __shared__ uint32_t Bs_hi[16*BLD2],  Bs_lo[16*BLD2];

    int bx = blockIdx.x;
    int mat   = bx >> 1;               // 0=Q 1=K 2=V
    int ncol0 = (bx & 1) * 128;
    int m0    = blockIdx.y * 128;

    const float* A = (mat == 0) ? q : kv;
    const float* W = (mat == 0) ? g_Wqe : (mat == 1 ? Wk : Wv);
    float* Out = (mat == 0) ? g_Q : (mat == 1 ? g_K : g_V);

    int t = threadIdx.x;
    int lane = t & 31, wid = t >> 5;
    int wm = wid & 3, wn = wid >> 2;
    int g = lane >> 2, tg = lane & 3;

    float c[2][8][4];
#pragma unroll
    for (int mt = 0; mt < 2; mt++)
#pragma unroll
        for (int nt = 0; nt < 8; nt++)
#pragma unroll
            for (int j = 0; j < 4; j++) c[mt][nt][j] = 0.f;

    for (int k0 = 0; k0 < EMB; k0 += 32) {
        // A tile: 128 x 32 floats -> pairs along k
#pragma unroll
        for (int i = 0; i < 4; i++) {
            int lin = t + i * 256;
            int r = lin >> 3, c4 = (lin & 7) * 4;
            float4 v = *(const float4*)&A[(size_t)(m0 + r) * EMB + k0 + c4];
            int k2 = c4 >> 1;
            split2(v.x, v.y, As_hi[r*ALD2 + k2],     As_lo[r*ALD2 + k2]);
            split2(v.z, v.w, As_hi[r*ALD2 + k2 + 1], As_lo[r*ALD2 + k2 + 1]);
        }
        // B tile: 32 x 128 floats -> pairs along k
#pragma unroll
        for (int j = 0; j < 8; j++) {
            int idx = t + j * 256;          // over 16 k2 x 128 n
            int k2 = idx >> 7, n = idx & 127;
            const float* wp = &W[(size_t)(k0 + 2*k2) * NPROJ + ncol0 + n];
            split2(wp[0], wp[NPROJ], Bs_hi[k2*BLD2 + n], Bs_lo[k2*BLD2 + n]);
        }
        __syncthreads();
#pragma unroll
        for (int kt = 0; kt < 2; kt++) {
            uint32_t ah[2][4], al[2][4];
#pragma unroll
            for (int mt = 0; mt < 2; mt++) {
                int mr = wm * 32 + mt * 16 + g;
                int b0 = mr * ALD2 + kt * 8 + tg;
                ah[mt][0] = As_hi[b0];            al[mt][0] = As_lo[b0];
                ah[mt][1] = As_hi[b0 + 8*ALD2];   al[mt][1] = As_lo[b0 + 8*ALD2];
                ah[mt][2] = As_hi[b0 + 4];        al[mt][2] = As_lo[b0 + 4];
                ah[mt][3] = As_hi[b0 + 8*ALD2+4]; al[mt][3] = As_lo[b0 + 8*ALD2+4];
            }
#pragma unroll
            for (int nt = 0; nt < 8; nt++) {
                int nn = wn * 64 + nt * 8 + g;
                uint32_t bh[2], bl[2];
                bh[0] = Bs_hi[(kt*8+tg)*BLD2 + nn];   bh[1] = Bs_hi[(kt*8+tg+4)*BLD2 + nn];
                bl[0] = Bs_lo[(kt*8+tg)*BLD2 + nn];   bl[1] = Bs_lo[(kt*8+tg+4)*BLD2 + nn];
                mma16(c[0][nt], ah[0], bh);
                mma16(c[0][nt], ah[0], bl);
                mma16(c[0][nt], al[0], bh);
                mma16(c[1][nt], ah[1], bh);
                mma16(c[1][nt], ah[1], bl);
                mma16(c[1][nt], al[1], bh);
            }
        }
        __syncthreads();
    }

#pragma unroll
    for (int mt = 0; mt < 2; mt++) {
#pragma unroll
        for (int nt = 0; nt < 8; nt++) {
            int row  = m0 + wm * 32 + mt * 16 + g;
            int ncol = ncol0 + wn * 64 + nt * 8 + 2 * tg;
            int h = ncol >> 6, d = ncol & 63;
#pragma unroll
            for (int rr = 0; rr < 2; rr++) {
                int r2 = row + rr * 8;
                int bb = r2 >> 11, ss = r2 & 2047;
                float x1 = c[mt][nt][rr*2+0];
                float x2 = c[mt][nt][rr*2+1];
                float* dst = &Out[(((size_t)bb * KVH + h) * SEQ + ss) * HD + d];
                if (mat < 2) {
                    float freq = powf(10000.0f, -(float)d * (1.0f/64.0f));
                    float sn, cs; sincosf((float)ss * freq, &sn, &cs);
                    *(float2*)dst = make_float2(x1*cs - x2*sn, x1*sn + x2*cs);
                } else {
                    *(float2*)dst = make_float2(x1, x2);
                }
            }
        }
    }
}

// ---------------------------------------------------------------------------
// Kernel 3: flash attention (bf16x3 tensor). 128 Q rows per block, 8 warps.
// Ks: [key][d2]  stride 36;  Vs: [key2][d] stride 72;  P per-warp [row][key2] stride 40.
// ---------------------------------------------------------------------------
#define KSLD 36
#define VSLD 72
#define PLD  40
__global__ __launch_bounds__(256) void flash_kernel() {
    extern __shared__ uint32_t sm[];
    uint32_t* Ks_hi = sm;                       // 64*36
    uint32_t* Ks_lo = sm + 64*KSLD;             // +2304
    uint32_t* Vs_hi = sm + 2*64*KSLD;           // 32*72
    uint32_t* Vs_lo = sm + 2*64*KSLD + 32*VSLD;
    uint32_t* Pr    = sm + 2*64*KSLD + 2*32*VSLD;  // 128*80 (Q staging, then per-warp P)

    int t = threadIdx.x;
    int lane = t & 31, wid = t >> 5;
    int g = lane >> 2, tg = lane & 3;
    int bh = blockIdx.y;
    size_t base = (size_t)bh * SEQ * HD;
    int q0 = blockIdx.x * 128;

    // stage raw Q (fp32 bits), stride 80
#pragma unroll
    for (int i = 0; i < 8; i++) {
        int lin = t + i * 256;
        int r = lin >> 4, c4 = (lin & 15) * 4;
        float4 v = *(const float4*)&g_Q[base + (size_t)(q0 + r) * HD + c4];
        Pr[r*80 + c4+0] = __float_as_uint(v.x);
        Pr[r*80 + c4+1] = __float_as_uint(v.y);
        Pr[r*80 + c4+2] = __float_as_uint(v.z);
        Pr[r*80 + c4+3] = __float_as_uint(v.w);
    }
    __syncthreads();

    // build Q fragments (hi/lo), scale 1/8 folded in
    uint32_t qh[4][4], ql[4][4];
    {
        int mr = wid * 16 + g;
#pragma unroll
        for (int kt = 0; kt < 4; kt++) {
            int k2a = kt * 8 + tg;
            float x0 = 0.125f * __uint_as_float(Pr[mr*80 + 2*k2a]);
            float x1 = 0.125f * __uint_as_float(Pr[mr*80 + 2*k2a + 1]);
            split2(x0, x1, qh[kt][0], ql[kt][0]);
            x0 = 0.125f * __uint_as_float(Pr[(mr+8)*80 + 2*k2a]);
            x1 = 0.125f * __uint_as_float(Pr[(mr+8)*80 + 2*k2a + 1]);
            split2(x0, x1, qh[kt][1], ql[kt][1]);
            x0 = 0.125f * __uint_as_float(Pr[mr*80 + 2*(k2a+4)]);
            x1 = 0.125f * __uint_as_float(Pr[mr*80 + 2*(k2a+4) + 1]);
            split2(x0, x1, qh[kt][2], ql[kt][2]);
            x0 = 0.125f * __uint_as_float(Pr[(mr+8)*80 + 2*(k2a+4)]);
            x1 = 0.125f * __uint_as_float(Pr[(mr+8)*80 + 2*(k2a+4) + 1]);
            split2(x0, x1, qh[kt][3], ql[kt][3]);
        }
    }

    float m0 = -CUDART_INF_F, m1 = -CUDART_INF_F, l0 = 0.f, l1 = 0.f;
    float o[8][4];
#pragma unroll
    for (int nt = 0; nt < 8; nt++)
#pragma unroll
        for (int j = 0; j < 4; j++) o[nt][j] = 0.f;

    const float* Kg = &g_K[base];
    const float* Vg = &g_V[base];
    uint32_t* Pw_hi = Pr + wid * 1280;          // warp's own 16 Q rows region (16*80)
    uint32_t* Pw_lo = Pw_hi + 16 * PLD;         // 640 + 640 = 1280

    for (int kt0 = 0; kt0 < SEQ; kt0 += 64) {
        // K tile: pairs along d, layout [key][d2]
#pragma unroll
        for (int i = 0; i < 4; i++) {
            int lin = t + i * 256;
            int r = lin >> 4, c4 = (lin & 15) * 4;
            float4 kvv = *(const float4*)&Kg[(size_t)(kt0 + r) * HD + c4];
            int k2 = c4 >> 1;
            split2(kvv.x, kvv.y, Ks_hi[r*KSLD + k2],     Ks_lo[r*KSLD + k2]);
            split2(kvv.z, kvv.w, Ks_hi[r*KSLD + k2 + 1], Ks_lo[r*KSLD + k2 + 1]);
        }
        // V tile: pairs along key, layout [key2][d]
#pragma unroll
        for (int j = 0; j < 8; j++) {
            int idx = t + j * 256;              // over 32 key2 x 64 d
            int k2 = idx >> 6, d = idx & 63;
            float v0 = Vg[(size_t)(kt0 + 2*k2) * HD + d];
            float v1 = Vg[(size_t)(kt0 + 2*k2 + 1) * HD + d];
            split2(v0, v1, Vs_hi[k2*VSLD + d], Vs_lo[k2*VSLD + d]);
        }
        __syncthreads();

        // S = Q K^T
        float s[8][4];
#pragma unroll
        for (int nt = 0; nt < 8; nt++)
#pragma unroll
            for (int j = 0; j < 4; j++) s[nt][j] = 0.f;
#pragma unroll
        for (int kt = 0; kt < 4; kt++) {
            int d2 = kt * 8 + tg;
#pragma unroll
            for (int nt = 0; nt < 8; nt++) {
                int kr = nt * 8 + g;
                uint32_t bhp[2], blp[2];
                bhp[0] = Ks_hi[kr*KSLD + d2];     bhp[1] = Ks_hi[kr*KSLD + d2 + 4];
                blp[0] = Ks_lo[kr*KSLD + d2];     blp[1] = Ks_lo[kr*KSLD + d2 + 4];
                mma16(s[nt], qh[kt], bhp);
                mma16(s[nt], qh[kt], blp);
                mma16(s[nt], ql[kt], bhp);
            }
        }

        // online softmax
        float mx0 = -CUDART_INF_F, mx1 = -CUDART_INF_F;
#pragma unroll
        for (int nt = 0; nt < 8; nt++) {
            mx0 = fmaxf(mx0, fmaxf(s[nt][0], s[nt][1]));
            mx1 = fmaxf(mx1, fmaxf(s[nt][2], s[nt][3]));
        }
        mx0 = fmaxf(mx0, __shfl_xor_sync(0xffffffffu, mx0, 1));
        mx0 = fmaxf(mx0, __shfl_xor_sync(0xffffffffu, mx0, 2));
        mx1 = fmaxf(mx1, __shfl_xor_sync(0xffffffffu, mx1, 1));
        mx1 = fmaxf(mx1, __shfl_xor_sync(0xffffffffu, mx1, 2));
        float mn0 = fmaxf(m0, mx0), mn1 = fmaxf(m1, mx1);
        float f0 = __expf(m0 - mn0), f1 = __expf(m1 - mn1);
        float s0 = 0.f, s1 = 0.f;
#pragma unroll
        for (int nt = 0; nt < 8; nt++) {
            s[nt][0] = __expf(s[nt][0] - mn0); s0 += s[nt][0];
            s[nt][1] = __expf(s[nt][1] - mn0); s0 += s[nt][1];
            s[nt][2] = __expf(s[nt][2] - mn1); s1 += s[nt][2];
            s[nt][3] = __expf(s[nt][3] - mn1); s1 += s[nt][3];
        }
        s0 += __shfl_xor_sync(0xffffffffu, s0, 1);
        s0 += __shfl_xor_sync(0xffffffffu, s0, 2);
        s1 += __shfl_xor_sync(0xffffffffu, s1, 1);
        s1 += __shfl_xor_sync(0xffffffffu, s1, 2);
        l0 = l0 * f0 + s0; l1 = l1 * f1 + s1;
        m0 = mn0; m1 = mn1;
#pragma unroll
        for (int nt = 0; nt < 8; nt++) {
            o[nt][0] *= f0; o[nt][1] *= f0;
            o[nt][2] *= f1; o[nt][3] *= f1;
        }

        // P -> per-warp smem as hi/lo pairs along key
#pragma unroll
        for (int nt = 0; nt < 8; nt++) {
            int kc2 = nt * 4 + tg;
            split2(s[nt][0], s[nt][1], Pw_hi[g*PLD + kc2],     Pw_lo[g*PLD + kc2]);
            split2(s[nt][2], s[nt][3], Pw_hi[(g+8)*PLD + kc2], Pw_lo[(g+8)*PLD + kc2]);
        }
        __syncwarp();

        // O += P V
#pragma unroll
        for (int kt = 0; kt < 4; kt++) {
            int kc2 = kt * 8 + tg;
            uint32_t ah2[4], al2[4];
            ah2[0] = Pw_hi[g*PLD + kc2];         al2[0] = Pw_lo[g*PLD + kc2];
            ah2[1] = Pw_hi[(g+8)*PLD + kc2];     al2[1] = Pw_lo[(g+8)*PLD + kc2];
            ah2[2] = Pw_hi[g*PLD + kc2 + 4];     al2[2] = Pw_lo[g*PLD + kc2 + 4];
            ah2[3] = Pw_hi[(g+8)*PLD + kc2 + 4]; al2[3] = Pw_lo[(g+8)*PLD + kc2 + 4];
#pragma unroll
            for (int nt = 0; nt < 8; nt++) {
                int nn = nt * 8 + g;
                uint32_t bhp[2], blp[2];
                bhp[0] = Vs_hi[kc2*VSLD + nn];     bhp[1] = Vs_hi[(kc2+4)*VSLD + nn];
                blp[0] = Vs_lo[kc2*VSLD + nn];     blp[1] = Vs_lo[(kc2+4)*VSLD + nn];
                mma16(o[nt], ah2, bhp);
                mma16(o[nt], ah2, blp);
                mma16(o[nt], al2, bhp);
            }
        }
        __syncthreads();
    }

    float inv0 = 1.f / l0, inv1 = 1.f / l1;
    int row = q0 + wid * 16 + g;
#pragma unroll
    for (int nt = 0; nt < 8; nt++) {
        int d = nt * 8 + 2 * tg;
        *(float2*)&g_O[base + (size_t)row * HD + d]       = make_float2(o[nt][0]*inv0, o[nt][1]*inv0);
        *(float2*)&g_O[base + (size_t)(row + 8) * HD + d] = make_float2(o[nt][2]*inv1, o[nt][3]*inv1);
    }
}

// ---------------------------------------------------------------------------
// Kernel 4: out = (mean_h g_O) @ Wo (bf16x3). Block 128x128, K=64.
// As: [m][k2] stride 36;  Bs: [k2][n] stride 136.
// ---------------------------------------------------------------------------
#define OALD2 36
#define OBLD2 136
__global__ __launch_bounds__(256) void out_kernel(const float* __restrict__ Wo,
                                                  float* __restrict__ out) {
    extern __shared__ uint32_t osm[];
    uint32_t* As_hi = osm;                      // 128*36
    uint32_t* As_lo = osm + 128*OALD2;
    uint32_t* Bs_hi = osm + 2*128*OALD2;        // 32*136
    uint32_t* Bs_lo = osm + 2*128*OALD2 + 32*OBLD2;

    int t = threadIdx.x;
    int lane = t & 31, wid = t >> 5;
    int wm = wid & 3, wn = wid >> 2;
    int g = lane >> 2, tg = lane & 3;
    int m0 = blockIdx.y * 128, n0 = blockIdx.x * 128;

    // A = mean over heads
#pragma unroll
    for (int i = 0; i < 8; i++) {
        int lin = t + i * 256;
        int r = lin >> 4, c4 = (lin & 15) * 4;
        int grow = m0 + r;
        int bb = grow >> 11, ss = grow & 2047;
        float ax = 0.f, ay = 0.f, az = 0.f, aw = 0.f;
#pragma unroll
        for (int h = 0; h < KVH; h++) {
            float4 v = *(const float4*)&g_O[(((size_t)bb * KVH + h) * SEQ + ss) * HD + c4];
            ax += v.x; ay += v.y; az += v.z; aw += v.w;
        }
        int k2 = c4 >> 1;
        split2(ax*0.25f, ay*0.25f, As_hi[r*OALD2 + k2],     As_lo[r*OALD2 + k2]);
        split2(az*0.25f, aw*0.25f, As_hi[r*OALD2 + k2 + 1], As_lo[r*OALD2 + k2 + 1]);
    }
    // B = Wo tile, pairs along k
#pragma unroll
    for (int j = 0; j < 16; j++) {
        int idx = t + j * 256;                  // 32 k2 x 128 n
        int k2 = idx >> 7, n = idx & 127;
        float w0 = Wo[(size_t)(2*k2) * EMB + n0 + n];
        float w1 = Wo[(size_t)(2*k2 + 1) * EMB + n0 + n];
        split2(w0, w1, Bs_hi[k2*OBLD2 + n], Bs_lo[k2*OBLD2 + n]);
    }
    __syncthreads();

    float c[2][8][4];
#pragma unroll
    for (int mt = 0; mt < 2; mt++)
#pragma unroll
        for (int nt = 0; nt < 8; nt++)
#pragma unroll
            for (int j = 0; j < 4; j++) c[mt][nt][j] = 0.f;

#pragma unroll
    for (int kt = 0; kt < 4; kt++) {
        uint32_t ah[2][4], al[2][4];
#pragma unroll
        for (int mt = 0; mt < 2; mt++) {
            int mr = wm * 32 + mt * 16 + g;
            int b0 = mr * OALD2 + kt * 8 + tg;
            ah[mt][0] = As_hi[b0];              al[mt][0] = As_lo[b0];
            ah[mt][1] = As_hi[b0 + 8*OALD2];    al[mt][1] = As_lo[b0 + 8*OALD2];
            ah[mt][2] = As_hi[b0 + 4];          al[mt][2] = As_lo[b0 + 4];
            ah[mt][3] = As_hi[b0 + 8*OALD2+4];  al[mt][3] = As_lo[b0 + 8*OALD2+4];
        }
#pragma unroll
        for (int nt = 0; nt < 8; nt++) {
            int nn = wn * 64 + nt * 8 + g;
            uint32_t bh[2], bl[2];
            bh[0] = Bs_hi[(kt*8+tg)*OBLD2 + nn];   bh[1] = Bs_hi[(kt*8+tg+4)*OBLD2 + nn];
            bl[0] = Bs_lo[(kt*8+tg)*OBLD2 + nn];   bl[1] = Bs_lo[(kt*8+tg+4)*OBLD2 + nn];
            mma16(c[0][nt], ah[0], bh);
            mma16(c[0][nt], ah[0], bl);
            mma16(c[0][nt], al[0], bh);
            mma16(c[1][nt], ah[1], bh);
            mma16(c[1][nt], ah[1], bl);
            mma16(c[1][nt], al[1], bh);
        }
    }

#pragma unroll
    for (int mt = 0; mt < 2; mt++) {
#pragma unroll
        for (int nt = 0; nt < 8; nt++) {
            int row = m0 + wm * 32 + mt * 16 + g;
            int col = n0 + wn * 64 + nt * 8 + 2 * tg;
            *(float2*)&out[(size_t)row * EMB + col]       = make_float2(c[mt][nt][0], c[mt][nt][1]);
            *(float2*)&out[(size_t)(row + 8) * EMB + col] = make_float2(c[mt][nt][2], c[mt][nt][3]);
        }
    }
}

// ---------------------------------------------------------------------------
extern "C" void kernel_launch(void* const* d_in, const int* in_sizes, int n_in,
                              void* d_out, int out_size) {
    const float* q  = (const float*)d_in[0];
    const float* kv = (const float*)d_in[1];
    const float* Wq = (const float*)d_in[2];
    const float* Wk = (const float*)d_in[3];
    const float* Wv = (const float*)d_in[4];
    const float* Wo = (const float*)d_in[5];
    float* out = (float*)d_out;

    const int flash_smem = (2*64*KSLD + 2*32*VSLD + 128*80) * 4;     // 77824 B
    const int out_smem   = (2*128*OALD2 + 2*32*OBLD2) * 4;           // 71680 B
    cudaFuncSetAttribute(flash_kernel, cudaFuncAttributeMaxDynamicSharedMemorySize, flash_smem);
    cudaFuncSetAttribute(out_kernel,   cudaFuncAttributeMaxDynamicSharedMemorySize, out_smem);

    fold_wq_kernel<<<(EMB * NPROJ) / 256, 256>>>(Wq);
    proj_kernel<<<dim3(6, MROWS / 128), 256>>>(q, kv, Wk, Wv);
    flash_kernel<<<dim3(SEQ / 128, BATCH * KVH), 256, flash_smem>>>();
    out_kernel<<<dim3(EMB / 128, MROWS / 128), 256, out_smem>>>(Wo, out);
}

// round 5
// speedup vs baseline: 2.6265x; 1.2803x over previous
#include <cuda_runtime.h>
#include <cuda_bf16.h>
#include <math_constants.h>
#include <stdint.h>

#define BATCH 4
#define SEQ   2048
#define EMB   1024
#define KVH   4
#define QHN   16
#define GRP   4
#define HD    64
#define NPROJ 256
#define MROWS (BATCH*SEQ)

__device__ float g_Wqe[EMB * NPROJ];
__device__ float g_Q[BATCH*KVH*SEQ*HD];
__device__ float g_K[BATCH*KVH*SEQ*HD];
__device__ float g_V[BATCH*KVH*SEQ*HD];
__device__ float g_O[BATCH*KVH*SEQ*HD];
__device__ float2 g_rope[SEQ * 32];          // (cos, sin) per (s, d/2)

// ---- helpers ---------------------------------------------------------------
__device__ __forceinline__ uint32_t pack_bf2(float x, float y) {
    __nv_bfloat162 h = __floats2bfloat162_rn(x, y);
    return *reinterpret_cast<uint32_t*>(&h);
}
__device__ __forceinline__ void split2(float x, float y, uint32_t& hi, uint32_t& lo) {
    __nv_bfloat162 h = __floats2bfloat162_rn(x, y);
    float2 hf = __bfloat1622float2(h);
    hi = *reinterpret_cast<uint32_t*>(&h);
    lo = pack_bf2(x - hf.x, y - hf.y);
}
__device__ __forceinline__ void mma16(float c[4], const uint32_t a[4], const uint32_t b[2]) {
    asm volatile("mma.sync.aligned.m16n8k16.row.col.f32.bf16.bf16.f32 "
        "{%0,%1,%2,%3}, {%4,%5,%6,%7}, {%8,%9}, {%0,%1,%2,%3};\n"
        : "+f"(c[0]), "+f"(c[1]), "+f"(c[2]), "+f"(c[3])
        : "r"(a[0]), "r"(a[1]), "r"(a[2]), "r"(a[3]), "r"(b[0]), "r"(b[1]));
}
__device__ __forceinline__ void ldsm4(uint32_t r[4], uint32_t addr) {
    asm volatile("ldmatrix.sync.aligned.m8n8.x4.shared.b16 {%0,%1,%2,%3}, [%4];"
        : "=r"(r[0]), "=r"(r[1]), "=r"(r[2]), "=r"(r[3]) : "r"(addr) : "memory");
}

// ---------------------------------------------------------------------------
// Kernel 0a: fold Wq over groups. 0b: RoPE table.
// ---------------------------------------------------------------------------
__global__ void fold_wq_kernel(const float* __restrict__ Wq) {
    int i = blockIdx.x * blockDim.x + threadIdx.x;
    int e  = i >> 8;
    int hd = i & 255;
    int h  = hd >> 6;
    int d  = hd & 63;
    float s = 0.f;
#pragma unroll
    for (int g = 0; g < GRP; g++)
        s += Wq[e * (QHN * HD) + (h * GRP + g) * HD + d];
    g_Wqe[i] = s;
}
__global__ void rope_table_kernel() {
    int i = blockIdx.x * blockDim.x + threadIdx.x;   // SEQ*32
    int s = i >> 5, d2 = i & 31;
    float freq = powf(10000.0f, -(float)(2*d2) * (1.0f/64.0f));
    float sn, cs; sincosf((float)s * freq, &sn, &cs);
    g_rope[i] = make_float2(cs, sn);
}

// ---------------------------------------------------------------------------
// Kernel 2: QKV projection (bf16x3) + RoPE epilogue (table).
// Block 128x128, K-tile 32, 8 warps (4x2). A via ldmatrix, B scalar.
// ALL smem in ONE extern array with explicit offsets (adjacency guaranteed).
// ---------------------------------------------------------------------------
#define ALD2 20
#define BLD2 136
// word offsets inside proj smem
#define P_AHI 0
#define P_ALO (128*ALD2)
#define P_BHI (2*128*ALD2)
#define P_BLO (2*128*ALD2 + 16*BLD2)
#define PROJ_SMEM_WORDS (2*128*ALD2 + 2*16*BLD2)
__global__ __launch_bounds__(256, 2) void proj_kernel(const float* __restrict__ q,
                            const float* __restrict__ kv,
                            const float* __restrict__ Wk,
                            const float* __restrict__ Wv) {
    extern __shared__ uint32_t psm[];
    uint32_t* As_hi = psm + P_AHI;
    uint32_t* As_lo = psm + P_ALO;
    uint32_t* Bs_hi = psm + P_BHI;
    uint32_t* Bs_lo = psm + P_BLO;

    int bx = blockIdx.x;
    int mat   = bx >> 1;
    int ncol0 = (bx & 1) * 128;
    int m0    = blockIdx.y * 128;

    const float* A = (mat == 0) ? q : kv;
    const float* W = (mat == 0) ? g_Wqe : (mat == 1 ? Wk : Wv);
    float* Out = (mat == 0) ? g_Q : (mat == 1 ? g_K : g_V);

    int t = threadIdx.x;
    int lane = t & 31, wid = t >> 5;
    int wm = wid & 3, wn = wid >> 2;
    int g = lane >> 2, tg = lane & 3;
    int l15 = lane & 15, lhi4 = (lane >> 4) << 2;

    uint32_t sbase = (uint32_t)__cvta_generic_to_shared(psm);
    uint32_t a_hi_base = sbase + ((wm*32 + l15)*ALD2 + lhi4) * 4;
    uint32_t a_lo_base = a_hi_base + P_ALO*4;

    float c[2][8][4];
#pragma unroll
    for (int mt = 0; mt < 2; mt++)
#pragma unroll
        for (int nt = 0; nt < 8; nt++)
#pragma unroll
            for (int j = 0; j < 4; j++) c[mt][nt][j] = 0.f;

    for (int k0 = 0; k0 < EMB; k0 += 32) {
#pragma unroll
        for (int i = 0; i < 4; i++) {
            int lin = t + i * 256;
            int r = lin >> 3, c4 = (lin & 7) * 4;
            float4 v = *(const float4*)&A[(size_t)(m0 + r) * EMB + k0 + c4];
            int k2 = c4 >> 1;
            split2(v.x, v.y, As_hi[r*ALD2 + k2],     As_lo[r*ALD2 + k2]);
            split2(v.z, v.w, As_hi[r*ALD2 + k2 + 1], As_lo[r*ALD2 + k2 + 1]);
        }
#pragma unroll
        for (int j = 0; j < 8; j++) {
            int idx = t + j * 256;
            int k2 = idx >> 7, n = idx & 127;
            const float* wp = &W[(size_t)(k0 + 2*k2) * NPROJ + ncol0 + n];
            split2(wp[0], wp[NPROJ], Bs_hi[k2*BLD2 + n], Bs_lo[k2*BLD2 + n]);
        }
        __syncthreads();
#pragma unroll
        for (int kt = 0; kt < 2; kt++) {
            uint32_t ah[2][4], al[2][4];
#pragma unroll
            for (int mt = 0; mt < 2; mt++) {
                ldsm4(ah[mt], a_hi_base + (mt*16*ALD2 + kt*8)*4);
                ldsm4(al[mt], a_lo_base + (mt*16*ALD2 + kt*8)*4);
            }
#pragma unroll
            for (int nt = 0; nt < 8; nt++) {
                int nn = wn * 64 + nt * 8 + g;
                uint32_t bh[2], bl[2];
                bh[0] = Bs_hi[(kt*8+tg)*BLD2 + nn];   bh[1] = Bs_hi[(kt*8+tg+4)*BLD2 + nn];
                bl[0] = Bs_lo[(kt*8+tg)*BLD2 + nn];   bl[1] = Bs_lo[(kt*8+tg+4)*BLD2 + nn];
                mma16(c[0][nt], ah[0], bh);
                mma16(c[0][nt], ah[0], bl);
                mma16(c[0][nt], al[0], bh);
                mma16(c[1][nt], ah[1], bh);
                mma16(c[1][nt], ah[1], bl);
                mma16(c[1][nt], al[1], bh);
            }
        }
        __syncthreads();
    }

#pragma unroll
    for (int mt = 0; mt < 2; mt++) {
#pragma unroll
        for (int nt = 0; nt < 8; nt++) {
            int row  = m0 + wm * 32 + mt * 16 + g;
            int ncol = ncol0 + wn * 64 + nt * 8 + 2 * tg;
            int h = ncol >> 6, d = ncol & 63;
#pragma unroll
            for (int rr = 0; rr < 2; rr++) {
                int r2 = row + rr * 8;
                int bb = r2 >> 11, ss = r2 & 2047;
                float x1 = c[mt][nt][rr*2+0];
                float x2 = c[mt][nt][rr*2+1];
                float* dst = &Out[(((size_t)bb * KVH + h) * SEQ + ss) * HD + d];
                if (mat < 2) {
                    float2 cssn = g_rope[ss * 32 + (d >> 1)];
                    *(float2*)dst = make_float2(x1*cssn.x - x2*cssn.y, x1*cssn.y + x2*cssn.x);
                } else {
                    *(float2*)dst = make_float2(x1, x2);
                }
            }
        }
    }
}

// ---------------------------------------------------------------------------
// Kernel 3: flash attention (bf16x3). 128 Q rows/block, 8 warps.
// Q/P/K operands via ldmatrix; V scalar. Single extern smem array.
// ---------------------------------------------------------------------------
#define QLD3 36
#define KLD3 36
#define VLD3 72
#define PLD3 36
__global__ __launch_bounds__(256, 2) void flash_kernel() {
    extern __shared__ uint32_t sm[];
    uint32_t* Qs_hi = sm;                         // 128*36
    uint32_t* Qs_lo = Qs_hi + 128*QLD3;
    uint32_t* Ks_hi = Qs_lo + 128*QLD3;           // 64*36
    uint32_t* Ks_lo = Ks_hi + 64*KLD3;
    uint32_t* Vs_hi = Ks_lo + 64*KLD3;            // 32*72
    uint32_t* Vs_lo = Vs_hi + 32*VLD3;
    uint32_t* Ps    = Vs_lo + 32*VLD3;            // 8 warps * 2*16*36

    int t = threadIdx.x;
    int lane = t & 31, wid = t >> 5;
    int g = lane >> 2, tg = lane & 3;
    int l15 = lane & 15, lhi4 = (lane >> 4) << 2, l7 = lane & 7;
    int bh = blockIdx.y;
    size_t base = (size_t)bh * SEQ * HD;
    int q0 = blockIdx.x * 128;

    uint32_t sbase = (uint32_t)__cvta_generic_to_shared(sm);
    uint32_t q_hi_base = sbase + ((wid*16 + l15)*QLD3 + lhi4) * 4;
    uint32_t q_lo_base = q_hi_base + 128*QLD3*4;
    uint32_t k_hi_base = sbase + (2*128*QLD3)*4
                       + (l7*KLD3 + ((lane>>3)&1)*4 + (lane>>4)*8) * 4;
    uint32_t k_lo_base = k_hi_base + 64*KLD3*4;
    uint32_t p_words = 2*128*QLD3 + 2*64*KLD3 + 2*32*VLD3 + wid*(2*16*PLD3);
    uint32_t p_hi_base = sbase + p_words*4 + (l15*PLD3 + lhi4)*4;
    uint32_t p_lo_base = p_hi_base + 16*PLD3*4;
    uint32_t* Pw_hi = Ps + wid*(2*16*PLD3);
    uint32_t* Pw_lo = Pw_hi + 16*PLD3;

    // load + split Q (scale 1/8 folded)
#pragma unroll
    for (int i = 0; i < 8; i++) {
        int lin = t + i * 256;
        int r = lin >> 4, c4 = (lin & 15) * 4;
        float4 v = *(const float4*)&g_Q[base + (size_t)(q0 + r) * HD + c4];
        int k2 = c4 >> 1;
        split2(0.125f*v.x, 0.125f*v.y, Qs_hi[r*QLD3 + k2],     Qs_lo[r*QLD3 + k2]);
        split2(0.125f*v.z, 0.125f*v.w, Qs_hi[r*QLD3 + k2 + 1], Qs_lo[r*QLD3 + k2 + 1]);
    }

    float m0 = -CUDART_INF_F, m1 = -CUDART_INF_F, l0 = 0.f, l1 = 0.f;
    float o[8][4];
#pragma unroll
    for (int nt = 0; nt < 8; nt++)
#pragma unroll
        for (int j = 0; j < 4; j++) o[nt][j] = 0.f;

    const float* Kg = &g_K[base];
    const float* Vg = &g_V[base];
    __syncthreads();

    for (int kt0 = 0; kt0 < SEQ; kt0 += 64) {
#pragma unroll
        for (int i = 0; i < 4; i++) {
            int lin = t + i * 256;
            int r = lin >> 4, c4 = (lin & 15) * 4;
            float4 kvv = *(const float4*)&Kg[(size_t)(kt0 + r) * HD + c4];
            int k2 = c4 >> 1;
            split2(kvv.x, kvv.y, Ks_hi[r*KLD3 + k2],     Ks_lo[r*KLD3 + k2]);
            split2(kvv.z, kvv.w, Ks_hi[r*KLD3 + k2 + 1], Ks_lo[r*KLD3 + k2 + 1]);
        }
#pragma unroll
        for (int j = 0; j < 8; j++) {
            int idx = t + j * 256;
            int k2 = idx >> 6, d = idx & 63;
            float v0 = Vg[(size_t)(kt0 + 2*k2) * HD + d];
            float v1 = Vg[(size_t)(kt0 + 2*k2 + 1) * HD + d];
            split2(v0, v1, Vs_hi[k2*VLD3 + d], Vs_lo[k2*VLD3 + d]);
        }
        __syncthreads();

        // ---- S = Q K^T ----
        float s[8][4];
#pragma unroll
        for (int nt = 0; nt < 8; nt++)
#pragma unroll
            for (int j = 0; j < 4; j++) s[nt][j] = 0.f;
#pragma unroll
        for (int ktp = 0; ktp < 2; ktp++) {
            uint32_t qh0[4], qh1[4], ql0[4], ql1[4];
            ldsm4(qh0, q_hi_base + (ktp*2+0)*32);
            ldsm4(qh1, q_hi_base + (ktp*2+1)*32);
            ldsm4(ql0, q_lo_base + (ktp*2+0)*32);
            ldsm4(ql1, q_lo_base + (ktp*2+1)*32);
#pragma unroll
            for (int nt = 0; nt < 8; nt++) {
                uint32_t kh[4], klo[4];
                uint32_t off = (uint32_t)(nt*8*KLD3 + ktp*16)*4;
                ldsm4(kh,  k_hi_base + off);
                ldsm4(klo, k_lo_base + off);
                mma16(s[nt], qh0, kh);
                mma16(s[nt], qh0, klo);
                mma16(s[nt], ql0, kh);
                mma16(s[nt], qh1, kh+2);
                mma16(s[nt], qh1, klo+2);
                mma16(s[nt], ql1, kh+2);
            }
        }

        // ---- online softmax ----
        float mx0 = -CUDART_INF_F, mx1 = -CUDART_INF_F;
#pragma unroll
        for (int nt = 0; nt < 8; nt++) {
            mx0 = fmaxf(mx0, fmaxf(s[nt][0], s[nt][1]));
            mx1 = fmaxf(mx1, fmaxf(s[nt][2], s[nt][3]));
        }
        mx0 = fmaxf(mx0, __shfl_xor_sync(0xffffffffu, mx0, 1));
        mx0 = fmaxf(mx0, __shfl_xor_sync(0xffffffffu, mx0, 2));
        mx1 = fmaxf(mx1, __shfl_xor_sync(0xffffffffu, mx1, 1));
        mx1 = fmaxf(mx1, __shfl_xor_sync(0xffffffffu, mx1, 2));
        float mn0 = fmaxf(m0, mx0), mn1 = fmaxf(m1, mx1);
        float f0 = __expf(m0 - mn0), f1 = __expf(m1 - mn1);
        float s0 = 0.f, s1 = 0.f;
#pragma unroll
        for (int nt = 0; nt < 8; nt++) {
            s[nt][0] = __expf(s[nt][0] - mn0); s0 += s[nt][0];
            s[nt][1] = __expf(s[nt][1] - mn0); s0 += s[nt][1];
            s[nt][2] = __expf(s[nt][2] - mn1); s1 += s[nt][2];
            s[nt][3] = __expf(s[nt][3] - mn1); s1 += s[nt][3];
        }
        s0 += __shfl_xor_sync(0xffffffffu, s0, 1);
        s0 += __shfl_xor_sync(0xffffffffu, s0, 2);
        s1 += __shfl_xor_sync(0xffffffffu, s1, 1);
        s1 += __shfl_xor_sync(0xffffffffu, s1, 2);
        l0 = l0 * f0 + s0; l1 = l1 * f1 + s1;
        m0 = mn0; m1 = mn1;
#pragma unroll
        for (int nt = 0; nt < 8; nt++) {
            o[nt][0] *= f0; o[nt][1] *= f0;
            o[nt][2] *= f1; o[nt][3] *= f1;
        }

        // P -> per-warp smem
#pragma unroll
        for (int nt = 0; nt < 8; nt++) {
            int kc2 = nt * 4 + tg;
            split2(s[nt][0], s[nt][1], Pw_hi[g*PLD3 + kc2],     Pw_lo[g*PLD3 + kc2]);
            split2(s[nt][2], s[nt][3], Pw_hi[(g+8)*PLD3 + kc2], Pw_lo[(g+8)*PLD3 + kc2]);
        }
        __syncwarp();

        // ---- O += P V ----
#pragma unroll
        for (int ktp = 0; ktp < 2; ktp++) {
            uint32_t ph0[4], ph1[4], pl0[4], pl1[4];
            ldsm4(ph0, p_hi_base + (ktp*2+0)*32);
            ldsm4(ph1, p_hi_base + (ktp*2+1)*32);
            ldsm4(pl0, p_lo_base + (ktp*2+0)*32);
            ldsm4(pl1, p_lo_base + (ktp*2+1)*32);
            int kc2a = (2*ktp)*8 + tg;
            int kc2b = kc2a + 8;
#pragma unroll
            for (int nt = 0; nt < 8; nt++) {
                int nn = nt * 8 + g;
                uint32_t vh[4], vl[4];
                vh[0] = Vs_hi[kc2a*VLD3 + nn];      vh[1] = Vs_hi[(kc2a+4)*VLD3 + nn];
                vh[2] = Vs_hi[kc2b*VLD3 + nn];      vh[3] = Vs_hi[(kc2b+4)*VLD3 + nn];
                vl[0] = Vs_lo[kc2a*VLD3 + nn];      vl[1] = Vs_lo[(kc2a+4)*VLD3 + nn];
                vl[2] = Vs_lo[kc2b*VLD3 + nn];      vl[3] = Vs_lo[(kc2b+4)*VLD3 + nn];
                mma16(o[nt], ph0, vh);
                mma16(o[nt], ph0, vl);
                mma16(o[nt], pl0, vh);
                mma16(o[nt], ph1, vh+2);
                mma16(o[nt], ph1, vl+2);
                mma16(o[nt], pl1, vh+2);
            }
        }
        __syncthreads();
    }

    float inv0 = 1.f / l0, inv1 = 1.f / l1;
    int row = q0 + wid * 16 + g;
#pragma unroll
    for (int nt = 0; nt < 8; nt++) {
        int d = nt * 8 + 2 * tg;
        *(float2*)&g_O[base + (size_t)row * HD + d]       = make_float2(o[nt][0]*inv0, o[nt][1]*inv0);
        *(float2*)&g_O[base + (size_t)(row + 8) * HD + d] = make_float2(o[nt][2]*inv1, o[nt][3]*inv1);
    }
}

// ---------------------------------------------------------------------------
// Kernel 4: out = (mean_h g_O) @ Wo (bf16x3). Block 128x128, K=64. A via ldmatrix.
// ---------------------------------------------------------------------------
#define OALD2 36
#define OBLD2 136
__global__ __launch_bounds__(256, 2) void out_kernel(const float* __restrict__ Wo,
                                                     float* __restrict__ out) {
    extern __shared__ uint32_t osm[];
    uint32_t* As_hi = osm;
    uint32_t* As_lo = osm + 128*OALD2;
    uint32_t* Bs_hi = osm + 2*128*OALD2;
    uint32_t* Bs_lo = osm + 2*128*OALD2 + 32*OBLD2;

    int t = threadIdx.x;
    int lane = t & 31, wid = t >> 5;
    int wm = wid & 3, wn = wid >> 2;
    int g = lane >> 2, tg = lane & 3;
    int l15 = lane & 15, lhi4 = (lane >> 4) << 2;
    int m0 = blockIdx.y * 128, n0 = blockIdx.x * 128;

    uint32_t a_hi_base = (uint32_t)__cvta_generic_to_shared(osm)
                       + ((wm*32 + l15)*OALD2 + lhi4) * 4;
    uint32_t a_lo_base = a_hi_base + 128*OALD2*4;

#pragma unroll
    for (int i = 0; i < 8; i++) {
        int lin = t + i * 256;
        int r = lin >> 4, c4 = (lin & 15) * 4;
        int grow = m0 + r;
        int bb = grow >> 11, ss = grow & 2047;
        float ax = 0.f, ay = 0.f, az = 0.f, aw = 0.f;
#pragma unroll
        for (int h = 0; h < KVH; h++) {
            float4 v = *(const float4*)&g_O[(((size_t)bb * KVH + h) * SEQ + ss) * HD + c4];
            ax += v.x; ay += v.y; az += v.z; aw += v.w;
        }
        int k2 = c4 >> 1;
        split2(ax*0.25f, ay*0.25f, As_hi[r*OALD2 + k2],     As_lo[r*OALD2 + k2]);
        split2(az*0.25f, aw*0.25f, As_hi[r*OALD2 + k2 + 1], As_lo[r*OALD2 + k2 + 1]);
    }
#pragma unroll
    for (int j = 0; j < 16; j++) {
        int idx = t + j * 256;
        int k2 = idx >> 7, n = idx & 127;
        float w0 = Wo[(size_t)(2*k2) * EMB + n0 + n];
        float w1 = Wo[(size_t)(2*k2 + 1) * EMB + n0 + n];
        split2(w0, w1, Bs_hi[k2*OBLD2 + n], Bs_lo[k2*OBLD2 + n]);
    }
    __syncthreads();

    float c[2][8][4];
#pragma unroll
    for (int mt = 0; mt < 2; mt++)
#pragma unroll
        for (int nt = 0; nt < 8; nt++)
#pragma unroll
            for (int j = 0; j < 4; j++) c[mt][nt][j] = 0.f;

#pragma unroll
    for (int kt = 0; kt < 4; kt++) {
        uint32_t ah[2][4], al[2][4];
#pragma unroll
        for (int mt = 0; mt < 2; mt++) {
            ldsm4(ah[mt], a_hi_base + (mt*16*OALD2 + kt*8)*4);
            ldsm4(al[mt], a_lo_base + (mt*16*OALD2 + kt*8)*4);
        }
#pragma unroll
        for (int nt = 0; nt < 8; nt++) {
            int nn = wn * 64 + nt * 8 + g;
            uint32_t bh[2], bl[2];
            bh[0] = Bs_hi[(kt*8+tg)*OBLD2 + nn];   bh[1] = Bs_hi[(kt*8+tg+4)*OBLD2 + nn];
            bl[0] = Bs_lo[(kt*8+tg)*OBLD2 + nn];   bl[1] = Bs_lo[(kt*8+tg+4)*OBLD2 + nn];
            mma16(c[0][nt], ah[0], bh);
            mma16(c[0][nt], ah[0], bl);
            mma16(c[0][nt], al[0], bh);
            mma16(c[1][nt], ah[1], bh);
            mma16(c[1][nt], ah[1], bl);
            mma16(c[1][nt], al[1], bh);
        }
    }

#pragma unroll
    for (int mt = 0; mt < 2; mt++) {
#pragma unroll
        for (int nt = 0; nt < 8; nt++) {
            int row = m0 + wm * 32 + mt * 16 + g;
            int col = n0 + wn * 64 + nt * 8 + 2 * tg;
            *(float2*)&out[(size_t)row * EMB + col]       = make_float2(c[mt][nt][0], c[mt][nt][1]);
            *(float2*)&out[(size_t)(row + 8) * EMB + col] = make_float2(c[mt][nt][2], c[mt][nt][3]);
        }
    }
}

// ---------------------------------------------------------------------------
extern "C" void kernel_launch(void* const* d_in, const int* in_sizes, int n_in,
                              void* d_out, int out_size) {
    const float* q  = (const float*)d_in[0];
    const float* kv = (const float*)d_in[1];
    const float* Wq = (const float*)d_in[2];
    const float* Wk = (const float*)d_in[3];
    const float* Wv = (const float*)d_in[4];
    const float* Wo = (const float*)d_in[5];
    float* out = (float*)d_out;

    const int proj_smem  = PROJ_SMEM_WORDS * 4;                                     // 37888
    const int flash_smem = (2*128*QLD3 + 2*64*KLD3 + 2*32*VLD3 + 8*2*16*PLD3) * 4;  // 110592
    const int out_smem   = (2*128*OALD2 + 2*32*OBLD2) * 4;                          // 71680
    cudaFuncSetAttribute(flash_kernel, cudaFuncAttributeMaxDynamicSharedMemorySize, flash_smem);
    cudaFuncSetAttribute(out_kernel,   cudaFuncAttributeMaxDynamicSharedMemorySize, out_smem);

    fold_wq_kernel<<<(EMB * NPROJ) / 256, 256>>>(Wq);
    rope_table_kernel<<<(SEQ * 32) / 256, 256>>>();
    proj_kernel<<<dim3(6, MROWS / 128), 256, proj_smem>>>(q, kv, Wk, Wv);
    flash_kernel<<<dim3(SEQ / 128, BATCH * KVH), 256, flash_smem>>>();
    out_kernel<<<dim3(EMB / 128, MROWS / 128), 256, out_smem>>>(Wo, out);
}

// round 6
// speedup vs baseline: 2.8536x; 1.0865x over previous
#include <cuda_runtime.h>
#include <cuda_bf16.h>
#include <math_constants.h>
#include <stdint.h>

#define BATCH 4
#define SEQ   2048
#define EMB   1024
#define KVH   4
#define QHN   16
#define GRP   4
#define HD    64
#define NPROJ 256
#define MROWS (BATCH*SEQ)

// Pre-split storage: bf16 hi/lo planes (same byte count as fp32 originals)
__device__ uint32_t g_Whi[3*512*NPROJ], g_Wlo[3*512*NPROJ];      // [mat][k2][n] pairs along k
__device__ uint32_t g_Qh[BATCH*KVH*SEQ*32], g_Ql[BATCH*KVH*SEQ*32]; // [bh][s][d2] pairs along d
__device__ uint32_t g_Kh[BATCH*KVH*SEQ*32], g_Kl[BATCH*KVH*SEQ*32];
__device__ __nv_bfloat16 g_VhT[BATCH*KVH*HD*SEQ], g_VlT[BATCH*KVH*HD*SEQ]; // [bh][d][s]
__device__ float g_O[BATCH*KVH*SEQ*HD];
__device__ float2 g_rope[SEQ * 32];

// ---- helpers ---------------------------------------------------------------
__device__ __forceinline__ uint32_t pack_bf2(float x, float y) {
    __nv_bfloat162 h = __floats2bfloat162_rn(x, y);
    return *reinterpret_cast<uint32_t*>(&h);
}
__device__ __forceinline__ void split2(float x, float y, uint32_t& hi, uint32_t& lo) {
    __nv_bfloat162 h = __floats2bfloat162_rn(x, y);
    float2 hf = __bfloat1622float2(h);
    hi = *reinterpret_cast<uint32_t*>(&h);
    lo = pack_bf2(x - hf.x, y - hf.y);
}
__device__ __forceinline__ void mma16(float c[4], const uint32_t a[4], const uint32_t b[2]) {
    asm volatile("mma.sync.aligned.m16n8k16.row.col.f32.bf16.bf16.f32 "
        "{%0,%1,%2,%3}, {%4,%5,%6,%7}, {%8,%9}, {%0,%1,%2,%3};\n"
        : "+f"(c[0]), "+f"(c[1]), "+f"(c[2]), "+f"(c[3])
        : "r"(a[0]), "r"(a[1]), "r"(a[2]), "r"(a[3]), "r"(b[0]), "r"(b[1]));
}
__device__ __forceinline__ void ldsm4(uint32_t r[4], uint32_t addr) {
    asm volatile("ldmatrix.sync.aligned.m8n8.x4.shared.b16 {%0,%1,%2,%3}, [%4];"
        : "=r"(r[0]), "=r"(r[1]), "=r"(r[2]), "=r"(r[3]) : "r"(addr) : "memory");
}

// ---------------------------------------------------------------------------
// Kernel 0a: prep W — fold Wq over groups, split all weights into hi/lo planes.
// ---------------------------------------------------------------------------
__global__ void prep_w_kernel(const float* __restrict__ Wq,
                              const float* __restrict__ Wk,
                              const float* __restrict__ Wv) {
    int i = blockIdx.x * blockDim.x + threadIdx.x;    // 3*512*256
    int mat = i >> 17;
    int rem = i & 131071;
    int k2 = rem >> 8, n = rem & 255;
    float w0, w1;
    if (mat == 0) {
        int h = n >> 6, d = n & 63;
        w0 = 0.f; w1 = 0.f;
#pragma unroll
        for (int g = 0; g < GRP; g++) {
            w0 += Wq[(size_t)(2*k2)   * (QHN*HD) + (h*GRP + g)*HD + d];
            w1 += Wq[(size_t)(2*k2+1) * (QHN*HD) + (h*GRP + g)*HD + d];
        }
    } else {
        const float* W = (mat == 1) ? Wk : Wv;
        w0 = W[(size_t)(2*k2)   * NPROJ + n];
        w1 = W[(size_t)(2*k2+1) * NPROJ + n];
    }
    split2(w0, w1, g_Whi[i], g_Wlo[i]);
}
__global__ void rope_table_kernel() {
    int i = blockIdx.x * blockDim.x + threadIdx.x;
    int s = i >> 5, d2 = i & 31;
    float freq = powf(10000.0f, -(float)(2*d2) * (1.0f/64.0f));
    float sn, cs; sincosf((float)s * freq, &sn, &cs);
    g_rope[i] = make_float2(cs, sn);
}

// ---------------------------------------------------------------------------
// Kernel 2: QKV projection (bf16x3) + RoPE + pre-split epilogue.
// ---------------------------------------------------------------------------
#define ALD2 20
#define BLD2 136
#define P_ALO (128*ALD2)
#define P_BHI (2*128*ALD2)
#define P_BLO (2*128*ALD2 + 16*BLD2)
#define PROJ_SMEM_WORDS (2*128*ALD2 + 2*16*BLD2)
__global__ __launch_bounds__(256, 2) void proj_kernel(const float* __restrict__ q,
                                                      const float* __restrict__ kv) {
    extern __shared__ uint32_t psm[];
    uint32_t* As_hi = psm;
    uint32_t* As_lo = psm + P_ALO;
    uint32_t* Bs_hi = psm + P_BHI;
    uint32_t* Bs_lo = psm + P_BLO;

    int bx = blockIdx.x;
    int mat   = bx >> 1;
    int ncol0 = (bx & 1) * 128;
    int m0    = blockIdx.y * 128;

    const float* A = (mat == 0) ? q : kv;
    int matbase = mat << 17;

    int t = threadIdx.x;
    int lane = t & 31, wid = t >> 5;
    int wm = wid & 3, wn = wid >> 2;
    int g = lane >> 2, tg = lane & 3;
    int l15 = lane & 15, lhi4 = (lane >> 4) << 2;

    uint32_t sbase = (uint32_t)__cvta_generic_to_shared(psm);
    uint32_t a_hi_base = sbase + ((wm*32 + l15)*ALD2 + lhi4) * 4;
    uint32_t a_lo_base = a_hi_base + P_ALO*4;

    float c[2][8][4];
#pragma unroll
    for (int mt = 0; mt < 2; mt++)
#pragma unroll
        for (int nt = 0; nt < 8; nt++)
#pragma unroll
            for (int j = 0; j < 4; j++) c[mt][nt][j] = 0.f;

    for (int k0 = 0; k0 < EMB; k0 += 32) {
#pragma unroll
        for (int i = 0; i < 4; i++) {
            int lin = t + i * 256;
            int r = lin >> 3, c4 = (lin & 7) * 4;
            float4 v = *(const float4*)&A[(size_t)(m0 + r) * EMB + k0 + c4];
            int k2 = c4 >> 1;
            split2(v.x, v.y, As_hi[r*ALD2 + k2],     As_lo[r*ALD2 + k2]);
            split2(v.z, v.w, As_hi[r*ALD2 + k2 + 1], As_lo[r*ALD2 + k2 + 1]);
        }
        // B tile: pure uint4 copies from pre-split planes
#pragma unroll
        for (int j = 0; j < 2; j++) {
            int idx = t + j * 256;                 // 16 k2 x 32 n4
            int k2 = idx >> 5, n4 = (idx & 31) * 4;
            int gidx = matbase + ((k0 >> 1) + k2) * NPROJ + ncol0 + n4;
            *(uint4*)&Bs_hi[k2*BLD2 + n4] = *(const uint4*)&g_Whi[gidx];
            *(uint4*)&Bs_lo[k2*BLD2 + n4] = *(const uint4*)&g_Wlo[gidx];
        }
        __syncthreads();
#pragma unroll
        for (int kt = 0; kt < 2; kt++) {
            uint32_t ah[2][4], al[2][4];
#pragma unroll
            for (int mt = 0; mt < 2; mt++) {
                ldsm4(ah[mt], a_hi_base + (mt*16*ALD2 + kt*8)*4);
                ldsm4(al[mt], a_lo_base + (mt*16*ALD2 + kt*8)*4);
            }
#pragma unroll
            for (int nt = 0; nt < 8; nt++) {
                int nn = wn * 64 + nt * 8 + g;
                uint32_t bh[2], bl[2];
                bh[0] = Bs_hi[(kt*8+tg)*BLD2 + nn];   bh[1] = Bs_hi[(kt*8+tg+4)*BLD2 + nn];
                bl[0] = Bs_lo[(kt*8+tg)*BLD2 + nn];   bl[1] = Bs_lo[(kt*8+tg+4)*BLD2 + nn];
                mma16(c[0][nt], ah[0], bh);
                mma16(c[0][nt], ah[0], bl);
                mma16(c[0][nt], al[0], bh);
                mma16(c[1][nt], ah[1], bh);
                mma16(c[1][nt], ah[1], bl);
                mma16(c[1][nt], al[1], bh);
            }
        }
        __syncthreads();
    }

    // epilogue: rope (Q/K), then store pre-split planes
#pragma unroll
    for (int mt = 0; mt < 2; mt++) {
#pragma unroll
        for (int nt = 0; nt < 8; nt++) {
            int row  = m0 + wm * 32 + mt * 16 + g;
            int ncol = ncol0 + wn * 64 + nt * 8 + 2 * tg;
            int h = ncol >> 6, d = ncol & 63;
#pragma unroll
            for (int rr = 0; rr < 2; rr++) {
                int r2 = row + rr * 8;
                int bb = r2 >> 11, ss = r2 & 2047;
                float x1 = c[mt][nt][rr*2+0];
                float x2 = c[mt][nt][rr*2+1];
                int bh_ = bb * KVH + h;
                if (mat < 2) {
                    float2 cssn = g_rope[ss * 32 + (d >> 1)];
                    float y1 = x1*cssn.x - x2*cssn.y;
                    float y2 = x1*cssn.y + x2*cssn.x;
                    size_t idx = ((size_t)bh_ * SEQ + ss) * 32 + (d >> 1);
                    if (mat == 0) {
                        split2(y1 * 0.125f, y2 * 0.125f, g_Qh[idx], g_Ql[idx]);
                    } else {
                        split2(y1, y2, g_Kh[idx], g_Kl[idx]);
                    }
                } else {
                    size_t vb = ((size_t)bh_ * HD + d) * SEQ + ss;
                    __nv_bfloat16 h1 = __float2bfloat16_rn(x1);
                    __nv_bfloat16 h2 = __float2bfloat16_rn(x2);
                    g_VhT[vb]       = h1;
                    g_VhT[vb + SEQ] = h2;
                    g_VlT[vb]       = __float2bfloat16_rn(x1 - __bfloat162float(h1));
                    g_VlT[vb + SEQ] = __float2bfloat16_rn(x2 - __bfloat162float(h2));
                }
            }
        }
    }
}

// ---------------------------------------------------------------------------
// Kernel 3: flash attention. All operands via ldmatrix; smem fills = pure copies.
// smem (words): Qhi[128*36] Qlo[128*36] Khi[64*36] Klo[64*36] Vhi[64*36] Vlo[64*36]
//               P[8 warps][2 planes][16*36]
// ---------------------------------------------------------------------------
#define LDW 36
#define F_QLO (128*LDW)
#define F_KHI (2*128*LDW)
#define F_KLO (F_KHI + 64*LDW)
#define F_VHI (F_KHI + 2*64*LDW)
#define F_VLO (F_VHI + 64*LDW)
#define F_P   (F_VHI + 2*64*LDW)
#define FLASH_SMEM_WORDS (F_P + 8*2*16*LDW)
__global__ __launch_bounds__(256, 2) void flash_kernel() {
    extern __shared__ uint32_t sm[];
    uint32_t* Qs_hi = sm;
    uint32_t* Qs_lo = sm + F_QLO;
    uint32_t* Ks_hi = sm + F_KHI;
    uint32_t* Ks_lo = sm + F_KLO;

    int t = threadIdx.x;
    int lane = t & 31, wid = t >> 5;
    int g = lane >> 2, tg = lane & 3;
    int l15 = lane & 15, lhi4 = (lane >> 4) << 2, l7 = lane & 7;
    int bh = blockIdx.y;
    int q0 = blockIdx.x * 128;
    size_t qrow0 = (size_t)bh * SEQ + q0;
    size_t krow0 = (size_t)bh * SEQ;

    uint32_t sbase = (uint32_t)__cvta_generic_to_shared(sm);
    uint32_t q_hi_base = sbase + ((wid*16 + l15)*LDW + lhi4) * 4;
    uint32_t q_lo_base = q_hi_base + F_QLO*4;
    uint32_t k_hi_base = sbase + (F_KHI + l7*LDW + ((lane>>3)&1)*4 + (lane>>4)*8) * 4;
    uint32_t k_lo_base = k_hi_base + 64*LDW*4;
    uint32_t v_hi_base = sbase + (F_VHI + (l7 + (lane>>4)*8)*LDW + ((lane>>3)&1)*4) * 4;
    uint32_t v_lo_base = v_hi_base + 64*LDW*4;
    uint32_t p_hi_base = sbase + (F_P + wid*(2*16*LDW) + l15*LDW + lhi4) * 4;
    uint32_t p_lo_base = p_hi_base + 16*LDW*4;
    uint32_t* Pw_hi = sm + F_P + wid*(2*16*LDW);
    uint32_t* Pw_lo = Pw_hi + 16*LDW;

    // stage Q (pure copy, pre-scaled + pre-split in proj)
#pragma unroll
    for (int i = 0; i < 4; i++) {
        int lin = t + i * 256;
        int r = lin >> 3, c4 = (lin & 7) * 4;
        *(uint4*)&Qs_hi[r*LDW + c4] = *(const uint4*)&g_Qh[(qrow0 + r)*32 + c4];
        *(uint4*)&Qs_lo[r*LDW + c4] = *(const uint4*)&g_Ql[(qrow0 + r)*32 + c4];
    }

    float m0 = -CUDART_INF_F, m1 = -CUDART_INF_F, l0 = 0.f, l1 = 0.f;
    float o[8][4];
#pragma unroll
    for (int nt = 0; nt < 8; nt++)
#pragma unroll
        for (int j = 0; j < 4; j++) o[nt][j] = 0.f;

    const __nv_bfloat16* VhT = g_VhT + (size_t)bh * HD * SEQ;
    const __nv_bfloat16* VlT = g_VlT + (size_t)bh * HD * SEQ;
    __syncthreads();

    for (int kt0 = 0; kt0 < SEQ; kt0 += 64) {
        // K tile copy
#pragma unroll
        for (int i = 0; i < 2; i++) {
            int lin = t + i * 256;
            int r = lin >> 3, c4 = (lin & 7) * 4;
            *(uint4*)&sm[F_KHI + r*LDW + c4] = *(const uint4*)&g_Kh[(krow0 + kt0 + r)*32 + c4];
            *(uint4*)&sm[F_KLO + r*LDW + c4] = *(const uint4*)&g_Kl[(krow0 + kt0 + r)*32 + c4];
        }
        // V tile copy (transposed planes, rows = d)
#pragma unroll
        for (int i = 0; i < 2; i++) {
            int lin = t + i * 256;
            int d = lin >> 3, u = lin & 7;
            *(uint4*)&sm[F_VHI + d*LDW + u*4] = ((const uint4*)(VhT + (size_t)d*SEQ + kt0))[u];
            *(uint4*)&sm[F_VLO + d*LDW + u*4] = ((const uint4*)(VlT + (size_t)d*SEQ + kt0))[u];
        }
        __syncthreads();

        // ---- S = Q K^T ----
        float s[8][4];
#pragma unroll
        for (int nt = 0; nt < 8; nt++)
#pragma unroll
            for (int j = 0; j < 4; j++) s[nt][j] = 0.f;
#pragma unroll
        for (int ktp = 0; ktp < 2; ktp++) {
            uint32_t qh0[4], qh1[4], ql0[4], ql1[4];
            ldsm4(qh0, q_hi_base + (ktp*2+0)*32);
            ldsm4(qh1, q_hi_base + (ktp*2+1)*32);
            ldsm4(ql0, q_lo_base + (ktp*2+0)*32);
            ldsm4(ql1, q_lo_base + (ktp*2+1)*32);
#pragma unroll
            for (int nt = 0; nt < 8; nt++) {
                uint32_t kh[4], klo[4];
                uint32_t off = (uint32_t)(nt*8*LDW + ktp*16)*4;
                ldsm4(kh,  k_hi_base + off);
                ldsm4(klo, k_lo_base + off);
                mma16(s[nt], qh0, kh);
                mma16(s[nt], qh0, klo);
                mma16(s[nt], ql0, kh);
                mma16(s[nt], qh1, kh+2);
                mma16(s[nt], qh1, klo+2);
                mma16(s[nt], ql1, kh+2);
            }
        }

        // ---- online softmax ----
        float mx0 = -CUDART_INF_F, mx1 = -CUDART_INF_F;
#pragma unroll
        for (int nt = 0; nt < 8; nt++) {
            mx0 = fmaxf(mx0, fmaxf(s[nt][0], s[nt][1]));
            mx1 = fmaxf(mx1, fmaxf(s[nt][2], s[nt][3]));
        }
        mx0 = fmaxf(mx0, __shfl_xor_sync(0xffffffffu, mx0, 1));
        mx0 = fmaxf(mx0, __shfl_xor_sync(0xffffffffu, mx0, 2));
        mx1 = fmaxf(mx1, __shfl_xor_sync(0xffffffffu, mx1, 1));
        mx1 = fmaxf(mx1, __shfl_xor_sync(0xffffffffu, mx1, 2));
        float mn0 = fmaxf(m0, mx0), mn1 = fmaxf(m1, mx1);
        float f0 = __expf(m0 - mn0), f1 = __expf(m1 - mn1);
        float s0 = 0.f, s1 = 0.f;
#pragma unroll
        for (int nt = 0; nt < 8; nt++) {
            s[nt][0] = __expf(s[nt][0] - mn0); s0 += s[nt][0];
            s[nt][1] = __expf(s[nt][1] - mn0); s0 += s[nt][1];
            s[nt][2] = __expf(s[nt][2] - mn1); s1 += s[nt][2];
            s[nt][3] = __expf(s[nt][3] - mn1); s1 += s[nt][3];
        }
        s0 += __shfl_xor_sync(0xffffffffu, s0, 1);
        s0 += __shfl_xor_sync(0xffffffffu, s0, 2);
        s1 += __shfl_xor_sync(0xffffffffu, s1, 1);
        s1 += __shfl_xor_sync(0xffffffffu, s1, 2);
        l0 = l0 * f0 + s0; l1 = l1 * f1 + s1;
        m0 = mn0; m1 = mn1;
#pragma unroll
        for (int nt = 0; nt < 8; nt++) {
            o[nt][0] *= f0; o[nt][1] *= f0;
            o[nt][2] *= f1; o[nt][3] *= f1;
        }

        // P -> per-warp smem (split)
#pragma unroll
        for (int nt = 0; nt < 8; nt++) {
            int kc2 = nt * 4 + tg;
            split2(s[nt][0], s[nt][1], Pw_hi[g*LDW + kc2],     Pw_lo[g*LDW + kc2]);
            split2(s[nt][2], s[nt][3], Pw_hi[(g+8)*LDW + kc2], Pw_lo[(g+8)*LDW + kc2]);
        }
        __syncwarp();

        // ---- O += P V  (all ldmatrix) ----
#pragma unroll
        for (int kc = 0; kc < 4; kc++) {
            uint32_t ph[4], pl[4];
            ldsm4(ph, p_hi_base + kc*32);
            ldsm4(pl, p_lo_base + kc*32);
#pragma unroll
            for (int n16 = 0; n16 < 4; n16++) {
                uint32_t vh4[4], vl4[4];
                uint32_t voff = (uint32_t)(n16*16*LDW + kc*8)*4;
                ldsm4(vh4, v_hi_base + voff);
                ldsm4(vl4, v_lo_base + voff);
                mma16(o[2*n16],   ph, vh4);
                mma16(o[2*n16],   ph, vl4);
                mma16(o[2*n16],   pl, vh4);
                mma16(o[2*n16+1], ph, vh4+2);
                mma16(o[2*n16+1], ph, vl4+2);
                mma16(o[2*n16+1], pl, vh4+2);
            }
        }
        __syncthreads();
    }

    float inv0 = 1.f / l0, inv1 = 1.f / l1;
    int row = q0 + wid * 16 + g;
    size_t obase = (size_t)bh * SEQ * HD;
#pragma unroll
    for (int nt = 0; nt < 8; nt++) {
        int d = nt * 8 + 2 * tg;
        *(float2*)&g_O[obase + (size_t)row * HD + d]       = make_float2(o[nt][0]*inv0, o[nt][1]*inv0);
        *(float2*)&g_O[obase + (size_t)(row + 8) * HD + d] = make_float2(o[nt][2]*inv1, o[nt][3]*inv1);
    }
}

// ---------------------------------------------------------------------------
// Kernel 4: out = (mean_h g_O) @ Wo (bf16x3). Unchanged from passing kernel.
// ---------------------------------------------------------------------------
#define OALD2 36
#define OBLD2 136
__global__ __launch_bounds__(256, 2) void out_kernel(const float* __restrict__ Wo,
                                                     float* __restrict__ out) {
    extern __shared__ uint32_t osm[];
    uint32_t* As_hi = osm;
    uint32_t* As_lo = osm + 128*OALD2;
    uint32_t* Bs_hi = osm + 2*128*OALD2;
    uint32_t* Bs_lo = osm + 2*128*OALD2 + 32*OBLD2;

    int t = threadIdx.x;
    int lane = t & 31, wid = t >> 5;
    int wm = wid & 3, wn = wid >> 2;
    int g = lane >> 2, tg = lane & 3;
    int l15 = lane & 15, lhi4 = (lane >> 4) << 2;
    int m0 = blockIdx.y * 128, n0 = blockIdx.x * 128;

    uint32_t a_hi_base = (uint32_t)__cvta_generic_to_shared(osm)
                       + ((wm*32 + l15)*OALD2 + lhi4) * 4;
    uint32_t a_lo_base = a_hi_base + 128*OALD2*4;

#pragma unroll
    for (int i = 0; i < 8; i++) {
        int lin = t + i * 256;
        int r = lin >> 4, c4 = (lin & 15) * 4;
        int grow = m0 + r;
        int bb = grow >> 11, ss = grow & 2047;
        float ax = 0.f, ay = 0.f, az = 0.f, aw = 0.f;
#pragma unroll
        for (int h = 0; h < KVH; h++) {
            float4 v = *(const float4*)&g_O[(((size_t)bb * KVH + h) * SEQ + ss) * HD + c4];
            ax += v.x; ay += v.y; az += v.z; aw += v.w;
        }
        int k2 = c4 >> 1;
        split2(ax*0.25f, ay*0.25f, As_hi[r*OALD2 + k2],     As_lo[r*OALD2 + k2]);
        split2(az*0.25f, aw*0.25f, As_hi[r*OALD2 + k2 + 1], As_lo[r*OALD2 + k2 + 1]);
    }
#pragma unroll
    for (int j = 0; j < 16; j++) {
        int idx = t + j * 256;
        int k2 = idx >> 7, n = idx & 127;
        float w0 = Wo[(size_t)(2*k2) * EMB + n0 + n];
        float w1 = Wo[(size_t)(2*k2 + 1) * EMB + n0 + n];
        split2(w0, w1, Bs_hi[k2*OBLD2 + n], Bs_lo[k2*OBLD2 + n]);
    }
    __syncthreads();

    float c[2][8][4];
#pragma unroll
    for (int mt = 0; mt < 2; mt++)
#pragma unroll
        for (int nt = 0; nt < 8; nt++)
#pragma unroll
            for (int j = 0; j < 4; j++) c[mt][nt][j] = 0.f;

#pragma unroll
    for (int kt = 0; kt < 4; kt++) {
        uint32_t ah[2][4], al[2][4];
#pragma unroll
        for (int mt = 0; mt < 2; mt++) {
            ldsm4(ah[mt], a_hi_base + (mt*16*OALD2 + kt*8)*4);
            ldsm4(al[mt], a_lo_base + (mt*16*OALD2 + kt*8)*4);
        }
#pragma unroll
        for (int nt = 0; nt < 8; nt++) {
            int nn = wn * 64 + nt * 8 + g;
            uint32_t bh[2], bl[2];
            bh[0] = Bs_hi[(kt*8+tg)*OBLD2 + nn];   bh[1] = Bs_hi[(kt*8+tg+4)*OBLD2 + nn];
            bl[0] = Bs_lo[(kt*8+tg)*OBLD2 + nn];   bl[1] = Bs_lo[(kt*8+tg+4)*OBLD2 + nn];
            mma16(c[0][nt], ah[0], bh);
            mma16(c[0][nt], ah[0], bl);
            mma16(c[0][nt], al[0], bh);
            mma16(c[1][nt], ah[1], bh);
            mma16(c[1][nt], ah[1], bl);
            mma16(c[1][nt], al[1], bh);
        }
    }

#pragma unroll
    for (int mt = 0; mt < 2; mt++) {
#pragma unroll
        for (int nt = 0; nt < 8; nt++) {
            int row = m0 + wm * 32 + mt * 16 + g;
            int col = n0 + wn * 64 + nt * 8 + 2 * tg;
            *(float2*)&out[(size_t)row * EMB + col]       = make_float2(c[mt][nt][0], c[mt][nt][1]);
            *(float2*)&out[(size_t)(row + 8) * EMB + col] = make_float2(c[mt][nt][2], c[mt][nt][3]);
        }
    }
}

// ---------------------------------------------------------------------------
extern "C" void kernel_launch(void* const* d_in, const int* in_sizes, int n_in,
                              void* d_out, int out_size) {
    const float* q  = (const float*)d_in[0];
    const float* kv = (const float*)d_in[1];
    const float* Wq = (const float*)d_in[2];
    const float* Wk = (const float*)d_in[3];
    const float* Wv = (const float*)d_in[4];
    const float* Wo = (const float*)d_in[5];
    float* out = (float*)d_out;

    const int proj_smem  = PROJ_SMEM_WORDS * 4;       // 37888
    const int flash_smem = FLASH_SMEM_WORDS * 4;      // 110592
    const int out_smem   = (2*128*OALD2 + 2*32*OBLD2) * 4;  // 71680
    cudaFuncSetAttribute(flash_kernel, cudaFuncAttributeMaxDynamicSharedMemorySize, flash_smem);
    cudaFuncSetAttribute(out_kernel,   cudaFuncAttributeMaxDynamicSharedMemorySize, out_smem);

    prep_w_kernel<<<(3*512*NPROJ) / 256, 256>>>(Wq, Wk, Wv);
    rope_table_kernel<<<(SEQ * 32) / 256, 256>>>();
    proj_kernel<<<dim3(6, MROWS / 128), 256, proj_smem>>>(q, kv);
    flash_kernel<<<dim3(SEQ / 128, BATCH * KVH), 256, flash_smem>>>();
    out_kernel<<<dim3(EMB / 128, MROWS / 128), 256, out_smem>>>(Wo, out);
}

// round 7
// speedup vs baseline: 2.9957x; 1.0498x over previous
#include <cuda_runtime.h>
#include <cuda_bf16.h>
#include <math_constants.h>
#include <stdint.h>

#define BATCH 4
#define SEQ   2048
#define EMB   1024
#define KVH   4
#define QHN   16
#define GRP   4
#define HD    64
#define NPROJ 256
#define MROWS (BATCH*SEQ)

// Pre-split storage: bf16 hi/lo planes
__device__ uint32_t g_Whi[3*512*NPROJ], g_Wlo[3*512*NPROJ];
__device__ uint32_t g_Qh[BATCH*KVH*SEQ*32], g_Ql[BATCH*KVH*SEQ*32];
__device__ uint32_t g_Kh[BATCH*KVH*SEQ*32], g_Kl[BATCH*KVH*SEQ*32];
__device__ __nv_bfloat16 g_VhT[BATCH*KVH*HD*SEQ], g_VlT[BATCH*KVH*HD*SEQ]; // [bh][d][s]
__device__ float g_O[BATCH*KVH*SEQ*HD];
__device__ float2 g_rope[SEQ * 32];

// ---- helpers ---------------------------------------------------------------
__device__ __forceinline__ uint32_t pack_bf2(float x, float y) {
    __nv_bfloat162 h = __floats2bfloat162_rn(x, y);
    return *reinterpret_cast<uint32_t*>(&h);
}
__device__ __forceinline__ void split2(float x, float y, uint32_t& hi, uint32_t& lo) {
    __nv_bfloat162 h = __floats2bfloat162_rn(x, y);
    float2 hf = __bfloat1622float2(h);
    hi = *reinterpret_cast<uint32_t*>(&h);
    lo = pack_bf2(x - hf.x, y - hf.y);
}
__device__ __forceinline__ void mma16(float c[4], const uint32_t a[4], const uint32_t b[2]) {
    asm volatile("mma.sync.aligned.m16n8k16.row.col.f32.bf16.bf16.f32 "
        "{%0,%1,%2,%3}, {%4,%5,%6,%7}, {%8,%9}, {%0,%1,%2,%3};\n"
        : "+f"(c[0]), "+f"(c[1]), "+f"(c[2]), "+f"(c[3])
        : "r"(a[0]), "r"(a[1]), "r"(a[2]), "r"(a[3]), "r"(b[0]), "r"(b[1]));
}
__device__ __forceinline__ void ldsm4(uint32_t r[4], uint32_t addr) {
    asm volatile("ldmatrix.sync.aligned.m8n8.x4.shared.b16 {%0,%1,%2,%3}, [%4];"
        : "=r"(r[0]), "=r"(r[1]), "=r"(r[2]), "=r"(r[3]) : "r"(addr) : "memory");
}
__device__ __forceinline__ void cpa16(uint32_t dst, const void* src) {
    asm volatile("cp.async.cg.shared.global [%0], [%1], 16;" :: "r"(dst), "l"(src));
}

// ---------------------------------------------------------------------------
// Kernel 0a: prep W.  0b: RoPE table.
// ---------------------------------------------------------------------------
__global__ void prep_w_kernel(const float* __restrict__ Wq,
                              const float* __restrict__ Wk,
                              const float* __restrict__ Wv) {
    int i = blockIdx.x * blockDim.x + threadIdx.x;
    int mat = i >> 17;
    int rem = i & 131071;
    int k2 = rem >> 8, n = rem & 255;
    float w0, w1;
    if (mat == 0) {
        int h = n >> 6, d = n & 63;
        w0 = 0.f; w1 = 0.f;
#pragma unroll
        for (int g = 0; g < GRP; g++) {
            w0 += Wq[(size_t)(2*k2)   * (QHN*HD) + (h*GRP + g)*HD + d];
            w1 += Wq[(size_t)(2*k2+1) * (QHN*HD) + (h*GRP + g)*HD + d];
        }
    } else {
        const float* W = (mat == 1) ? Wk : Wv;
        w0 = W[(size_t)(2*k2)   * NPROJ + n];
        w1 = W[(size_t)(2*k2+1) * NPROJ + n];
    }
    split2(w0, w1, g_Whi[i], g_Wlo[i]);
}
__global__ void rope_table_kernel() {
    int i = blockIdx.x * blockDim.x + threadIdx.x;
    int s = i >> 5, d2 = i & 31;
    float freq = powf(10000.0f, -(float)(2*d2) * (1.0f/64.0f));
    float sn, cs; sincosf((float)s * freq, &sn, &cs);
    g_rope[i] = make_float2(cs, sn);
}

// ---------------------------------------------------------------------------
// Kernel 2: QKV projection (bf16x3) + RoPE + pre-split epilogue. (unchanged)
// ---------------------------------------------------------------------------
#define ALD2 20
#define BLD2 136
#define P_ALO (128*ALD2)
#define P_BHI (2*128*ALD2)
#define P_BLO (2*128*ALD2 + 16*BLD2)
#define PROJ_SMEM_WORDS (2*128*ALD2 + 2*16*BLD2)
__global__ __launch_bounds__(256, 2) void proj_kernel(const float* __restrict__ q,
                                                      const float* __restrict__ kv) {
    extern __shared__ uint32_t psm[];
    uint32_t* As_hi = psm;
    uint32_t* As_lo = psm + P_ALO;
    uint32_t* Bs_hi = psm + P_BHI;
    uint32_t* Bs_lo = psm + P_BLO;

    int bx = blockIdx.x;
    int mat   = bx >> 1;
    int ncol0 = (bx & 1) * 128;
    int m0    = blockIdx.y * 128;

    const float* A = (mat == 0) ? q : kv;
    int matbase = mat << 17;

    int t = threadIdx.x;
    int lane = t & 31, wid = t >> 5;
    int wm = wid & 3, wn = wid >> 2;
    int g = lane >> 2, tg = lane & 3;
    int l15 = lane & 15, lhi4 = (lane >> 4) << 2;

    uint32_t sbase = (uint32_t)__cvta_generic_to_shared(psm);
    uint32_t a_hi_base = sbase + ((wm*32 + l15)*ALD2 + lhi4) * 4;
    uint32_t a_lo_base = a_hi_base + P_ALO*4;

    float c[2][8][4];
#pragma unroll
    for (int mt = 0; mt < 2; mt++)
#pragma unroll
        for (int nt = 0; nt < 8; nt++)
#pragma unroll
            for (int j = 0; j < 4; j++) c[mt][nt][j] = 0.f;

    for (int k0 = 0; k0 < EMB; k0 += 32) {
#pragma unroll
        for (int i = 0; i < 4; i++) {
            int lin = t + i * 256;
            int r = lin >> 3, c4 = (lin & 7) * 4;
            float4 v = *(const float4*)&A[(size_t)(m0 + r) * EMB + k0 + c4];
            int k2 = c4 >> 1;
            split2(v.x, v.y, As_hi[r*ALD2 + k2],     As_lo[r*ALD2 + k2]);
            split2(v.z, v.w, As_hi[r*ALD2 + k2 + 1], As_lo[r*ALD2 + k2 + 1]);
        }
#pragma unroll
        for (int j = 0; j < 2; j++) {
            int idx = t + j * 256;
            int k2 = idx >> 5, n4 = (idx & 31) * 4;
            int gidx = matbase + ((k0 >> 1) + k2) * NPROJ + ncol0 + n4;
            *(uint4*)&Bs_hi[k2*BLD2 + n4] = *(const uint4*)&g_Whi[gidx];
            *(uint4*)&Bs_lo[k2*BLD2 + n4] = *(const uint4*)&g_Wlo[gidx];
        }
        __syncthreads();
#pragma unroll
        for (int kt = 0; kt < 2; kt++) {
            uint32_t ah[2][4], al[2][4];
#pragma unroll
            for (int mt = 0; mt < 2; mt++) {
                ldsm4(ah[mt], a_hi_base + (mt*16*ALD2 + kt*8)*4);
                ldsm4(al[mt], a_lo_base + (mt*16*ALD2 + kt*8)*4);
            }
#pragma unroll
            for (int nt = 0; nt < 8; nt++) {
                int nn = wn * 64 + nt * 8 + g;
                uint32_t bh[2], bl[2];
                bh[0] = Bs_hi[(kt*8+tg)*BLD2 + nn];   bh[1] = Bs_hi[(kt*8+tg+4)*BLD2 + nn];
                bl[0] = Bs_lo[(kt*8+tg)*BLD2 + nn];   bl[1] = Bs_lo[(kt*8+tg+4)*BLD2 + nn];
                mma16(c[0][nt], ah[0], bh);
                mma16(c[0][nt], ah[0], bl);
                mma16(c[0][nt], al[0], bh);
                mma16(c[1][nt], ah[1], bh);
                mma16(c[1][nt], ah[1], bl);
                mma16(c[1][nt], al[1], bh);
            }
        }
        __syncthreads();
    }

#pragma unroll
    for (int mt = 0; mt < 2; mt++) {
#pragma unroll
        for (int nt = 0; nt < 8; nt++) {
            int row  = m0 + wm * 32 + mt * 16 + g;
            int ncol = ncol0 + wn * 64 + nt * 8 + 2 * tg;
            int h = ncol >> 6, d = ncol & 63;
#pragma unroll
            for (int rr = 0; rr < 2; rr++) {
                int r2 = row + rr * 8;
                int bb = r2 >> 11, ss = r2 & 2047;
                float x1 = c[mt][nt][rr*2+0];
                float x2 = c[mt][nt][rr*2+1];
                int bh_ = bb * KVH + h;
                if (mat < 2) {
                    float2 cssn = g_rope[ss * 32 + (d >> 1)];
                    float y1 = x1*cssn.x - x2*cssn.y;
                    float y2 = x1*cssn.y + x2*cssn.x;
                    size_t idx = ((size_t)bh_ * SEQ + ss) * 32 + (d >> 1);
                    if (mat == 0) {
                        split2(y1 * 0.125f, y2 * 0.125f, g_Qh[idx], g_Ql[idx]);
                    } else {
                        split2(y1, y2, g_Kh[idx], g_Kl[idx]);
                    }
                } else {
                    size_t vb = ((size_t)bh_ * HD + d) * SEQ + ss;
                    __nv_bfloat16 h1 = __float2bfloat16_rn(x1);
                    __nv_bfloat16 h2 = __float2bfloat16_rn(x2);
                    g_VhT[vb]       = h1;
                    g_VhT[vb + SEQ] = h2;
                    g_VlT[vb]       = __float2bfloat16_rn(x1 - __bfloat162float(h1));
                    g_VlT[vb + SEQ] = __float2bfloat16_rn(x2 - __bfloat162float(h2));
                }
            }
        }
    }
}

// ---------------------------------------------------------------------------
// Kernel 3: flash attention. Register-resident P (FA2 frag identity) +
// cp.async double-buffered K/V. smem: Q[2 planes 128x36] + 2 KV stages.
// Stage layout (words): Khi[64*36] Klo[64*36] Vhi[64*36] Vlo[64*36] = 9216.
// ---------------------------------------------------------------------------
#define LDW 36
#define F_QLO (128*LDW)
#define F_KV  (2*128*LDW)          // 9216: start of stage 0
#define SSTR  (4*64*LDW)           // 9216 words per stage
#define S_KLO (64*LDW)
#define S_VHI (2*64*LDW)
#define S_VLO (3*64*LDW)
#define FLASH_SMEM_WORDS (F_KV + 2*SSTR)   // 27648 words = 110592 B
__global__ __launch_bounds__(256, 2) void flash_kernel() {
    extern __shared__ uint32_t sm[];
    uint32_t* Qs_hi = sm;
    uint32_t* Qs_lo = sm + F_QLO;

    int t = threadIdx.x;
    int lane = t & 31, wid = t >> 5;
    int g = lane >> 2, tg = lane & 3;
    int l15 = lane & 15, lhi4 = (lane >> 4) << 2, l7 = lane & 7;
    int bh = blockIdx.y;
    int q0 = blockIdx.x * 128;
    size_t qrow0 = (size_t)bh * SEQ + q0;
    size_t krow0 = (size_t)bh * SEQ;

    uint32_t sbase = (uint32_t)__cvta_generic_to_shared(sm);
    uint32_t q_hi_base = sbase + ((wid*16 + l15)*LDW + lhi4) * 4;
    uint32_t q_lo_base = q_hi_base + F_QLO*4;
    // stage-0 fragment bases (add st*SSTR*4 for stage 1)
    uint32_t k_hi_base0 = sbase + (F_KV + l7*LDW + ((lane>>3)&1)*4 + (lane>>4)*8) * 4;
    uint32_t v_hi_base0 = sbase + (F_KV + S_VHI + (l7 + (lane>>4)*8)*LDW + ((lane>>3)&1)*4) * 4;

    const __nv_bfloat16* VhT = g_VhT + (size_t)bh * HD * SEQ;
    const __nv_bfloat16* VlT = g_VlT + (size_t)bh * HD * SEQ;

    // per-thread cp.async copy coordinates (2 quads per plane)
    int cr0 = t >> 3, cc0 = (t & 7) * 4;                 // rows 0..31
    int cr1 = (t + 256) >> 3, cc1 = ((t + 256) & 7) * 4; // rows 32..63

    // ---- prologue: stage 0 loads + Q staging ----
    {
        uint32_t d0 = sbase + (F_KV + cr0*LDW + cc0) * 4;
        uint32_t d1 = sbase + (F_KV + cr1*LDW + cc1) * 4;
        cpa16(d0,            &g_Kh[(krow0 + cr0)*32 + cc0]);
        cpa16(d1,            &g_Kh[(krow0 + cr1)*32 + cc1]);
        cpa16(d0 + S_KLO*4,  &g_Kl[(krow0 + cr0)*32 + cc0]);
        cpa16(d1 + S_KLO*4,  &g_Kl[(krow0 + cr1)*32 + cc1]);
        cpa16(d0 + S_VHI*4,  VhT + (size_t)cr0*SEQ + cc0*2);
        cpa16(d1 + S_VHI*4,  VhT + (size_t)cr1*SEQ + cc1*2);
        cpa16(d0 + S_VLO*4,  VlT + (size_t)cr0*SEQ + cc0*2);
        cpa16(d1 + S_VLO*4,  VlT + (size_t)cr1*SEQ + cc1*2);
        asm volatile("cp.async.commit_group;");
    }
#pragma unroll
    for (int i = 0; i < 4; i++) {
        int lin = t + i * 256;
        int r = lin >> 3, c4 = (lin & 7) * 4;
        *(uint4*)&Qs_hi[r*LDW + c4] = *(const uint4*)&g_Qh[(qrow0 + r)*32 + c4];
        *(uint4*)&Qs_lo[r*LDW + c4] = *(const uint4*)&g_Ql[(qrow0 + r)*32 + c4];
    }

    float m0 = -CUDART_INF_F, m1 = -CUDART_INF_F, l0 = 0.f, l1 = 0.f;
    float o[8][4];
#pragma unroll
    for (int nt = 0; nt < 8; nt++)
#pragma unroll
        for (int j = 0; j < 4; j++) o[nt][j] = 0.f;

    for (int it = 0; it < SEQ/64; it++) {
        // issue next-stage loads
        if (it + 1 < SEQ/64) {
            int kt1 = (it + 1) * 64;
            uint32_t stoff = (uint32_t)(((it + 1) & 1) * SSTR) * 4;
            uint32_t d0 = sbase + (F_KV + cr0*LDW + cc0) * 4 + stoff;
            uint32_t d1 = sbase + (F_KV + cr1*LDW + cc1) * 4 + stoff;
            cpa16(d0,            &g_Kh[(krow0 + kt1 + cr0)*32 + cc0]);
            cpa16(d1,            &g_Kh[(krow0 + kt1 + cr1)*32 + cc1]);
            cpa16(d0 + S_KLO*4,  &g_Kl[(krow0 + kt1 + cr0)*32 + cc0]);
            cpa16(d1 + S_KLO*4,  &g_Kl[(krow0 + kt1 + cr1)*32 + cc1]);
            cpa16(d0 + S_VHI*4,  VhT + (size_t)cr0*SEQ + kt1 + cc0*2);
            cpa16(d1 + S_VHI*4,  VhT + (size_t)cr1*SEQ + kt1 + cc1*2);
            cpa16(d0 + S_VLO*4,  VlT + (size_t)cr0*SEQ + kt1 + cc0*2);
            cpa16(d1 + S_VLO*4,  VlT + (size_t)cr1*SEQ + kt1 + cc1*2);
            asm volatile("cp.async.commit_group;");
            asm volatile("cp.async.wait_group 1;");
        } else {
            asm volatile("cp.async.wait_group 0;");
        }
        __syncthreads();

        uint32_t stoff = (uint32_t)((it & 1) * SSTR) * 4;
        uint32_t k_hi_base = k_hi_base0 + stoff;
        uint32_t k_lo_base = k_hi_base + S_KLO*4;
        uint32_t v_hi_base = v_hi_base0 + stoff;
        uint32_t v_lo_base = v_hi_base + 64*LDW*4;

        // ---- S = Q K^T ----
        float s[8][4];
#pragma unroll
        for (int nt = 0; nt < 8; nt++)
#pragma unroll
            for (int j = 0; j < 4; j++) s[nt][j] = 0.f;
#pragma unroll
        for (int ktp = 0; ktp < 2; ktp++) {
            uint32_t qh0[4], qh1[4], ql0[4], ql1[4];
            ldsm4(qh0, q_hi_base + (ktp*2+0)*32);
            ldsm4(qh1, q_hi_base + (ktp*2+1)*32);
            ldsm4(ql0, q_lo_base + (ktp*2+0)*32);
            ldsm4(ql1, q_lo_base + (ktp*2+1)*32);
#pragma unroll
            for (int nt = 0; nt < 8; nt++) {
                uint32_t kh[4], klo[4];
                uint32_t off = (uint32_t)(nt*8*LDW + ktp*16)*4;
                ldsm4(kh,  k_hi_base + off);
                ldsm4(klo, k_lo_base + off);
                mma16(s[nt], qh0, kh);
                mma16(s[nt], qh0, klo);
                mma16(s[nt], ql0, kh);
                mma16(s[nt], qh1, kh+2);
                mma16(s[nt], qh1, klo+2);
                mma16(s[nt], ql1, kh+2);
            }
        }

        // ---- online softmax ----
        float mx0 = -CUDART_INF_F, mx1 = -CUDART_INF_F;
#pragma unroll
        for (int nt = 0; nt < 8; nt++) {
            mx0 = fmaxf(mx0, fmaxf(s[nt][0], s[nt][1]));
            mx1 = fmaxf(mx1, fmaxf(s[nt][2], s[nt][3]));
        }
        mx0 = fmaxf(mx0, __shfl_xor_sync(0xffffffffu, mx0, 1));
        mx0 = fmaxf(mx0, __shfl_xor_sync(0xffffffffu, mx0, 2));
        mx1 = fmaxf(mx1, __shfl_xor_sync(0xffffffffu, mx1, 1));
        mx1 = fmaxf(mx1, __shfl_xor_sync(0xffffffffu, mx1, 2));
        float mn0 = fmaxf(m0, mx0), mn1 = fmaxf(m1, mx1);
        float f0 = __expf(m0 - mn0), f1 = __expf(m1 - mn1);
        float s0 = 0.f, s1 = 0.f;
#pragma unroll
        for (int nt = 0; nt < 8; nt++) {
            s[nt][0] = __expf(s[nt][0] - mn0); s0 += s[nt][0];
            s[nt][1] = __expf(s[nt][1] - mn0); s0 += s[nt][1];
            s[nt][2] = __expf(s[nt][2] - mn1); s1 += s[nt][2];
            s[nt][3] = __expf(s[nt][3] - mn1); s1 += s[nt][3];
        }
        s0 += __shfl_xor_sync(0xffffffffu, s0, 1);
        s0 += __shfl_xor_sync(0xffffffffu, s0, 2);
        s1 += __shfl_xor_sync(0xffffffffu, s1, 1);
        s1 += __shfl_xor_sync(0xffffffffu, s1, 2);
        l0 = l0 * f0 + s0; l1 = l1 * f1 + s1;
        m0 = mn0; m1 = mn1;
#pragma unroll
        for (int nt = 0; nt < 8; nt++) {
            o[nt][0] *= f0; o[nt][1] *= f0;
            o[nt][2] *= f1; o[nt][3] *= f1;
        }

        // ---- O += P V  (P built in registers via C->A fragment identity) ----
#pragma unroll
        for (int kc = 0; kc < 4; kc++) {
            uint32_t ah[4], al[4];
            split2(s[2*kc][0],   s[2*kc][1],   ah[0], al[0]);
            split2(s[2*kc][2],   s[2*kc][3],   ah[1], al[1]);
            split2(s[2*kc+1][0], s[2*kc+1][1], ah[2], al[2]);
            split2(s[2*kc+1][2], s[2*kc+1][3], ah[3], al[3]);
#pragma unroll
            for (int n16 = 0; n16 < 4; n16++) {
                uint32_t vh4[4], vl4[4];
                uint32_t voff = (uint32_t)(n16*16*LDW + kc*8)*4;
                ldsm4(vh4, v_hi_base + voff);
                ldsm4(vl4, v_lo_base + voff);
                mma16(o[2*n16],   ah, vh4);
                mma16(o[2*n16],   ah, vl4);
                mma16(o[2*n16],   al, vh4);
                mma16(o[2*n16+1], ah, vh4+2);
                mma16(o[2*n16+1], ah, vl4+2);
                mma16(o[2*n16+1], al, vh4+2);
            }
        }
        __syncthreads();
    }

    float inv0 = 1.f / l0, inv1 = 1.f / l1;
    int row = q0 + wid * 16 + g;
    size_t obase = (size_t)bh * SEQ * HD;
#pragma unroll
    for (int nt = 0; nt < 8; nt++) {
        int d = nt * 8 + 2 * tg;
        *(float2*)&g_O[obase + (size_t)row * HD + d]       = make_float2(o[nt][0]*inv0, o[nt][1]*inv0);
        *(float2*)&g_O[obase + (size_t)(row + 8) * HD + d] = make_float2(o[nt][2]*inv1, o[nt][3]*inv1);
    }
}

// ---------------------------------------------------------------------------
// Kernel 4: out = (mean_h g_O) @ Wo (bf16x3). (unchanged)
// ---------------------------------------------------------------------------
#define OALD2 36
#define OBLD2 136
__global__ __launch_bounds__(256, 2) void out_kernel(const float* __restrict__ Wo,
                                                     float* __restrict__ out) {
    extern __shared__ uint32_t osm[];
    uint32_t* As_hi = osm;
    uint32_t* As_lo = osm + 128*OALD2;
    uint32_t* Bs_hi = osm + 2*128*OALD2;
    uint32_t* Bs_lo = osm + 2*128*OALD2 + 32*OBLD2;

    int t = threadIdx.x;
    int lane = t & 31, wid = t >> 5;
    int wm = wid & 3, wn = wid >> 2;
    int g = lane >> 2, tg = lane & 3;
    int l15 = lane & 15, lhi4 = (lane >> 4) << 2;
    int m0 = blockIdx.y * 128, n0 = blockIdx.x * 128;

    uint32_t a_hi_base = (uint32_t)__cvta_generic_to_shared(osm)
                       + ((wm*32 + l15)*OALD2 + lhi4) * 4;
    uint32_t a_lo_base = a_hi_base + 128*OALD2*4;

#pragma unroll
    for (int i = 0; i < 8; i++) {
        int lin = t + i * 256;
        int r = lin >> 4, c4 = (lin & 15) * 4;
        int grow = m0 + r;
        int bb = grow >> 11, ss = grow & 2047;
        float ax = 0.f, ay = 0.f, az = 0.f, aw = 0.f;
#pragma unroll
        for (int h = 0; h < KVH; h++) {
            float4 v = *(const float4*)&g_O[(((size_t)bb * KVH + h) * SEQ + ss) * HD + c4];
            ax += v.x; ay += v.y; az += v.z; aw += v.w;
        }
        int k2 = c4 >> 1;
        split2(ax*0.25f, ay*0.25f, As_hi[r*OALD2 + k2],     As_lo[r*OALD2 + k2]);
        split2(az*0.25f, aw*0.25f, As_hi[r*OALD2 + k2 + 1], As_lo[r*OALD2 + k2 + 1]);
    }
#pragma unroll
    for (int j = 0; j < 16; j++) {
        int idx = t + j * 256;
        int k2 = idx >> 7, n = idx & 127;
        float w0 = Wo[(size_t)(2*k2) * EMB + n0 + n];
        float w1 = Wo[(size_t)(2*k2 + 1) * EMB + n0 + n];
        split2(w0, w1, Bs_hi[k2*OBLD2 + n], Bs_lo[k2*OBLD2 + n]);
    }
    __syncthreads();

    float c[2][8][4];
#pragma unroll
    for (int mt = 0; mt < 2; mt++)
#pragma unroll
        for (int nt = 0; nt < 8; nt++)
#pragma unroll
            for (int j = 0; j < 4; j++) c[mt][nt][j] = 0.f;

#pragma unroll
    for (int kt = 0; kt < 4; kt++) {
        uint32_t ah[2][4], al[2][4];
#pragma unroll
        for (int mt = 0; mt < 2; mt++) {
            ldsm4(ah[mt], a_hi_base + (mt*16*OALD2 + kt*8)*4);
            ldsm4(al[mt], a_lo_base + (mt*16*OALD2 + kt*8)*4);
        }
#pragma unroll
        for (int nt = 0; nt < 8; nt++) {
            int nn = wn * 64 + nt * 8 + g;
            uint32_t bh[2], bl[2];
            bh[0] = Bs_hi[(kt*8+tg)*OBLD2 + nn];   bh[1] = Bs_hi[(kt*8+tg+4)*OBLD2 + nn];
            bl[0] = Bs_lo[(kt*8+tg)*OBLD2 + nn];   bl[1] = Bs_lo[(kt*8+tg+4)*OBLD2 + nn];
            mma16(c[0][nt], ah[0], bh);
            mma16(c[0][nt], ah[0], bl);
            mma16(c[0][nt], al[0], bh);
            mma16(c[1][nt], ah[1], bh);
            mma16(c[1][nt], ah[1], bl);
            mma16(c[1][nt], al[1], bh);
        }
    }

#pragma unroll
    for (int mt = 0; mt < 2; mt++) {
#pragma unroll
        for (int nt = 0; nt < 8; nt++) {
            int row = m0 + wm * 32 + mt * 16 + g;
            int col = n0 + wn * 64 + nt * 8 + 2 * tg;
            *(float2*)&out[(size_t)row * EMB + col]       = make_float2(c[mt][nt][0], c[mt][nt][1]);
            *(float2*)&out[(size_t)(row + 8) * EMB + col] = make_float2(c[mt][nt][2], c[mt][nt][3]);
        }
    }
}

// ---------------------------------------------------------------------------
extern "C" void kernel_launch(void* const* d_in, const int* in_sizes, int n_in,
                              void* d_out, int out_size) {
    const float* q  = (const float*)d_in[0];
    const float* kv = (const float*)d_in[1];
    const float* Wq = (const float*)d_in[2];
    const float* Wk = (const float*)d_in[3];
    const float* Wv = (const float*)d_in[4];
    const float* Wo = (const float*)d_in[5];
    float* out = (float*)d_out;

    const int proj_smem  = PROJ_SMEM_WORDS * 4;             // 37888
    const int flash_smem = FLASH_SMEM_WORDS * 4;            // 110592
    const int out_smem   = (2*128*OALD2 + 2*32*OBLD2) * 4;  // 71680
    cudaFuncSetAttribute(flash_kernel, cudaFuncAttributeMaxDynamicSharedMemorySize, flash_smem);
    cudaFuncSetAttribute(out_kernel,   cudaFuncAttributeMaxDynamicSharedMemorySize, out_smem);

    prep_w_kernel<<<(3*512*NPROJ) / 256, 256>>>(Wq, Wk, Wv);
    rope_table_kernel<<<(SEQ * 32) / 256, 256>>>();
    proj_kernel<<<dim3(6, MROWS / 128), 256, proj_smem>>>(q, kv);
    flash_kernel<<<dim3(SEQ / 128, BATCH * KVH), 256, flash_smem>>>();
    out_kernel<<<dim3(EMB / 128, MROWS / 128), 256, out_smem>>>(Wo, out);
}

// round 8
// speedup vs baseline: 3.2285x; 1.0777x over previous
#include <cuda_runtime.h>
#include <cuda_bf16.h>
#include <math_constants.h>
#include <stdint.h>

#define BATCH 4
#define SEQ   2048
#define EMB   1024
#define KVH   4
#define QHN   16
#define GRP   4
#define HD    64
#define NPROJ 256
#define MROWS (BATCH*SEQ)
#define QSCALE 0.1803368801111244f   // 0.125 * log2(e)

// Pre-split storage: bf16 hi/lo planes
__device__ uint32_t g_Whi[3*512*NPROJ], g_Wlo[3*512*NPROJ];
__device__ uint32_t g_Qh[BATCH*KVH*SEQ*32], g_Ql[BATCH*KVH*SEQ*32];
__device__ uint32_t g_Kh[BATCH*KVH*SEQ*32], g_Kl[BATCH*KVH*SEQ*32];
__device__ __nv_bfloat16 g_VhT[BATCH*KVH*HD*SEQ], g_VlT[BATCH*KVH*HD*SEQ]; // [bh][d][s]
__device__ float g_O[BATCH*KVH*SEQ*HD];
__device__ float2 g_rope[SEQ * 32];

// ---- helpers ---------------------------------------------------------------
__device__ __forceinline__ uint32_t pack_bf2(float x, float y) {
    __nv_bfloat162 h = __floats2bfloat162_rn(x, y);
    return *reinterpret_cast<uint32_t*>(&h);
}
__device__ __forceinline__ void split2(float x, float y, uint32_t& hi, uint32_t& lo) {
    __nv_bfloat162 h = __floats2bfloat162_rn(x, y);
    float2 hf = __bfloat1622float2(h);
    hi = *reinterpret_cast<uint32_t*>(&h);
    lo = pack_bf2(x - hf.x, y - hf.y);
}
__device__ __forceinline__ void mma16(float c[4], const uint32_t a[4], const uint32_t b[2]) {
    asm volatile("mma.sync.aligned.m16n8k16.row.col.f32.bf16.bf16.f32 "
        "{%0,%1,%2,%3}, {%4,%5,%6,%7}, {%8,%9}, {%0,%1,%2,%3};\n"
        : "+f"(c[0]), "+f"(c[1]), "+f"(c[2]), "+f"(c[3])
        : "r"(a[0]), "r"(a[1]), "r"(a[2]), "r"(a[3]), "r"(b[0]), "r"(b[1]));
}
__device__ __forceinline__ void ldsm4(uint32_t r[4], uint32_t addr) {
    asm volatile("ldmatrix.sync.aligned.m8n8.x4.shared.b16 {%0,%1,%2,%3}, [%4];"
        : "=r"(r[0]), "=r"(r[1]), "=r"(r[2]), "=r"(r[3]) : "r"(addr) : "memory");
}
__device__ __forceinline__ void cpa16(uint32_t dst, const void* src) {
    asm volatile("cp.async.cg.shared.global [%0], [%1], 16;" :: "r"(dst), "l"(src));
}

// ---------------------------------------------------------------------------
// Kernel 0a: prep W.  0b: RoPE table.
// ---------------------------------------------------------------------------
__global__ void prep_w_kernel(const float* __restrict__ Wq,
                              const float* __restrict__ Wk,
                              const float* __restrict__ Wv) {
    int i = blockIdx.x * blockDim.x + threadIdx.x;
    int mat = i >> 17;
    int rem = i & 131071;
    int k2 = rem >> 8, n = rem & 255;
    float w0, w1;
    if (mat == 0) {
        int h = n >> 6, d = n & 63;
        w0 = 0.f; w1 = 0.f;
#pragma unroll
        for (int g = 0; g < GRP; g++) {
            w0 += Wq[(size_t)(2*k2)   * (QHN*HD) + (h*GRP + g)*HD + d];
            w1 += Wq[(size_t)(2*k2+1) * (QHN*HD) + (h*GRP + g)*HD + d];
        }
    } else {
        const float* W = (mat == 1) ? Wk : Wv;
        w0 = W[(size_t)(2*k2)   * NPROJ + n];
        w1 = W[(size_t)(2*k2+1) * NPROJ + n];
    }
    split2(w0, w1, g_Whi[i], g_Wlo[i]);
}
__global__ void rope_table_kernel() {
    int i = blockIdx.x * blockDim.x + threadIdx.x;
    int s = i >> 5, d2 = i & 31;
    float freq = powf(10000.0f, -(float)(2*d2) * (1.0f/64.0f));
    float sn, cs; sincosf((float)s * freq, &sn, &cs);
    g_rope[i] = make_float2(cs, sn);
}

// ---------------------------------------------------------------------------
// Kernel 2: QKV projection (bf16x3) + RoPE + pre-split epilogue.
// A-tile register-prefetched; B planes cp.async double-buffered.
// smem (words): Ahi[128*20] Alo[128*20] | B stage0 [hi 16*136 | lo 16*136] stage1 [...]
// ---------------------------------------------------------------------------
#define ALD2 20
#define BLD2 136
#define P_ALO (128*ALD2)
#define P_BHI (2*128*ALD2)
#define BSTG  (2*16*BLD2)          // 4352 words per B stage
#define BLO_OFF (16*BLD2)          // 2176
#define PROJ_SMEM_WORDS (P_BHI + 2*BSTG)   // 13824 words = 55296 B
__global__ __launch_bounds__(256, 2) void proj_kernel(const float* __restrict__ q,
                                                      const float* __restrict__ kv) {
    extern __shared__ uint32_t psm[];
    uint32_t* As_hi = psm;
    uint32_t* As_lo = psm + P_ALO;

    int bx = blockIdx.x;
    int mat   = bx >> 1;
    int ncol0 = (bx & 1) * 128;
    int m0    = blockIdx.y * 128;

    const float* A = (mat == 0) ? q : kv;
    int matbase = mat << 17;

    int t = threadIdx.x;
    int lane = t & 31, wid = t >> 5;
    int wm = wid & 3, wn = wid >> 2;
    int g = lane >> 2, tg = lane & 3;
    int l15 = lane & 15, lhi4 = (lane >> 4) << 2;

    uint32_t sbase = (uint32_t)__cvta_generic_to_shared(psm);
    uint32_t a_hi_base = sbase + ((wm*32 + l15)*ALD2 + lhi4) * 4;
    uint32_t a_lo_base = a_hi_base + P_ALO*4;

    float c[2][8][4];
#pragma unroll
    for (int mt = 0; mt < 2; mt++)
#pragma unroll
        for (int nt = 0; nt < 8; nt++)
#pragma unroll
            for (int j = 0; j < 4; j++) c[mt][nt][j] = 0.f;

    // prologue: A(0) into regs, B stage0 via cp.async
    float4 av[4];
#pragma unroll
    for (int i = 0; i < 4; i++) {
        int lin = t + i * 256;
        av[i] = *(const float4*)&A[(size_t)(m0 + (lin >> 3)) * EMB + (lin & 7) * 4];
    }
#pragma unroll
    for (int j = 0; j < 2; j++) {
        int idx = t + j * 256;
        int k2 = idx >> 5, n4 = (idx & 31) * 4;
        int gidx = matbase + k2 * NPROJ + ncol0 + n4;
        cpa16(sbase + (P_BHI + k2*BLD2 + n4) * 4,           &g_Whi[gidx]);
        cpa16(sbase + (P_BHI + BLO_OFF + k2*BLD2 + n4) * 4, &g_Wlo[gidx]);
    }
    asm volatile("cp.async.commit_group;");

    for (int k0 = 0; k0 < EMB; k0 += 32) {
        if (k0) __syncthreads();   // guard A smem reuse vs previous MMA readers
        // STS A(k0) from regs (split)
#pragma unroll
        for (int i = 0; i < 4; i++) {
            int lin = t + i * 256;
            int r = lin >> 3, c4 = (lin & 7) * 4;
            int k2 = c4 >> 1;
            split2(av[i].x, av[i].y, As_hi[r*ALD2 + k2],     As_lo[r*ALD2 + k2]);
            split2(av[i].z, av[i].w, As_hi[r*ALD2 + k2 + 1], As_lo[r*ALD2 + k2 + 1]);
        }
        if (k0 + 32 < EMB) {
            // prefetch next A into regs
#pragma unroll
            for (int i = 0; i < 4; i++) {
                int lin = t + i * 256;
                av[i] = *(const float4*)&A[(size_t)(m0 + (lin >> 3)) * EMB + k0 + 32 + (lin & 7) * 4];
            }
            // cp.async next B stage
            uint32_t bst = P_BHI + ((((k0 >> 5) + 1) & 1) ? BSTG : 0);
#pragma unroll
            for (int j = 0; j < 2; j++) {
                int idx = t + j * 256;
                int k2 = idx >> 5, n4 = (idx & 31) * 4;
                int gidx = matbase + (((k0 + 32) >> 1) + k2) * NPROJ + ncol0 + n4;
                cpa16(sbase + (bst + k2*BLD2 + n4) * 4,           &g_Whi[gidx]);
                cpa16(sbase + (bst + BLO_OFF + k2*BLD2 + n4) * 4, &g_Wlo[gidx]);
            }
            asm volatile("cp.async.commit_group;");
            asm volatile("cp.async.wait_group 1;");
        } else {
            asm volatile("cp.async.wait_group 0;");
        }
        __syncthreads();

        uint32_t* Bs_hi = psm + P_BHI + (((k0 >> 5) & 1) ? BSTG : 0);
        uint32_t* Bs_lo = Bs_hi + BLO_OFF;
#pragma unroll
        for (int kt = 0; kt < 2; kt++) {
            uint32_t ah[2][4], al[2][4];
#pragma unroll
            for (int mt = 0; mt < 2; mt++) {
                ldsm4(ah[mt], a_hi_base + (mt*16*ALD2 + kt*8)*4);
                ldsm4(al[mt], a_lo_base + (mt*16*ALD2 + kt*8)*4);
            }
#pragma unroll
            for (int nt = 0; nt < 8; nt++) {
                int nn = wn * 64 + nt * 8 + g;
                uint32_t bh[2], bl[2];
                bh[0] = Bs_hi[(kt*8+tg)*BLD2 + nn];   bh[1] = Bs_hi[(kt*8+tg+4)*BLD2 + nn];
                bl[0] = Bs_lo[(kt*8+tg)*BLD2 + nn];   bl[1] = Bs_lo[(kt*8+tg+4)*BLD2 + nn];
                mma16(c[0][nt], ah[0], bh);
                mma16(c[0][nt], ah[0], bl);
                mma16(c[0][nt], al[0], bh);
                mma16(c[1][nt], ah[1], bh);
                mma16(c[1][nt], ah[1], bl);
                mma16(c[1][nt], al[1], bh);
            }
        }
    }

    // epilogue: rope (Q/K), store pre-split planes (Q carries 0.125*log2e)
#pragma unroll
    for (int mt = 0; mt < 2; mt++) {
#pragma unroll
        for (int nt = 0; nt < 8; nt++) {
            int row  = m0 + wm * 32 + mt * 16 + g;
            int ncol = ncol0 + wn * 64 + nt * 8 + 2 * tg;
            int h = ncol >> 6, d = ncol & 63;
#pragma unroll
            for (int rr = 0; rr < 2; rr++) {
                int r2 = row + rr * 8;
                int bb = r2 >> 11, ss = r2 & 2047;
                float x1 = c[mt][nt][rr*2+0];
                float x2 = c[mt][nt][rr*2+1];
                int bh_ = bb * KVH + h;
                if (mat < 2) {
                    float2 cssn = g_rope[ss * 32 + (d >> 1)];
                    float y1 = x1*cssn.x - x2*cssn.y;
                    float y2 = x1*cssn.y + x2*cssn.x;
                    size_t idx = ((size_t)bh_ * SEQ + ss) * 32 + (d >> 1);
                    if (mat == 0) {
                        split2(y1 * QSCALE, y2 * QSCALE, g_Qh[idx], g_Ql[idx]);
                    } else {
                        split2(y1, y2, g_Kh[idx], g_Kl[idx]);
                    }
                } else {
                    size_t vb = ((size_t)bh_ * HD + d) * SEQ + ss;
                    __nv_bfloat16 h1 = __float2bfloat16_rn(x1);
                    __nv_bfloat16 h2 = __float2bfloat16_rn(x2);
                    g_VhT[vb]       = h1;
                    g_VhT[vb + SEQ] = h2;
                    g_VlT[vb]       = __float2bfloat16_rn(x1 - __bfloat162float(h1));
                    g_VlT[vb + SEQ] = __float2bfloat16_rn(x2 - __bfloat162float(h2));
                }
            }
        }
    }
}

// ---------------------------------------------------------------------------
// Kernel 3: flash attention. Reg-resident P + cp.async double-buffered K/V.
// Base-2 softmax (Q pre-scaled by 0.125*log2e in proj) -> exp2f everywhere.
// ---------------------------------------------------------------------------
#define LDW 36
#define F_QLO (128*LDW)
#define F_KV  (2*128*LDW)
#define SSTR  (4*64*LDW)
#define S_KLO (64*LDW)
#define S_VHI (2*64*LDW)
#define S_VLO (3*64*LDW)
#define FLASH_SMEM_WORDS (F_KV + 2*SSTR)   // 27648 words = 110592 B
__global__ __launch_bounds__(256, 2) void flash_kernel() {
    extern __shared__ uint32_t sm[];
    uint32_t* Qs_hi = sm;
    uint32_t* Qs_lo = sm + F_QLO;

    int t = threadIdx.x;
    int lane = t & 31, wid = t >> 5;
    int g = lane >> 2, tg = lane & 3;
    int l15 = lane & 15, lhi4 = (lane >> 4) << 2, l7 = lane & 7;
    int bh = blockIdx.y;
    int q0 = blockIdx.x * 128;
    size_t qrow0 = (size_t)bh * SEQ + q0;
    size_t krow0 = (size_t)bh * SEQ;

    uint32_t sbase = (uint32_t)__cvta_generic_to_shared(sm);
    uint32_t q_hi_base = sbase + ((wid*16 + l15)*LDW + lhi4) * 4;
    uint32_t q_lo_base = q_hi_base + F_QLO*4;
    uint32_t k_hi_base0 = sbase + (F_KV + l7*LDW + ((lane>>3)&1)*4 + (lane>>4)*8) * 4;
    uint32_t v_hi_base0 = sbase + (F_KV + S_VHI + (l7 + (lane>>4)*8)*LDW + ((lane>>3)&1)*4) * 4;

    const __nv_bfloat16* VhT = g_VhT + (size_t)bh * HD * SEQ;
    const __nv_bfloat16* VlT = g_VlT + (size_t)bh * HD * SEQ;

    int cr0 = t >> 3, cc0 = (t & 7) * 4;
    int cr1 = (t + 256) >> 3, cc1 = ((t + 256) & 7) * 4;

    {
        uint32_t d0 = sbase + (F_KV + cr0*LDW + cc0) * 4;
        uint32_t d1 = sbase + (F_KV + cr1*LDW + cc1) * 4;
        cpa16(d0,            &g_Kh[(krow0 + cr0)*32 + cc0]);
        cpa16(d1,            &g_Kh[(krow0 + cr1)*32 + cc1]);
        cpa16(d0 + S_KLO*4,  &g_Kl[(krow0 + cr0)*32 + cc0]);
        cpa16(d1 + S_KLO*4,  &g_Kl[(krow0 + cr1)*32 + cc1]);
        cpa16(d0 + S_VHI*4,  VhT + (size_t)cr0*SEQ + cc0*2);
        cpa16(d1 + S_VHI*4,  VhT + (size_t)cr1*SEQ + cc1*2);
        cpa16(d0 + S_VLO*4,  VlT + (size_t)cr0*SEQ + cc0*2);
        cpa16(d1 + S_VLO*4,  VlT + (size_t)cr1*SEQ + cc1*2);
        asm volatile("cp.async.commit_group;");
    }
#pragma unroll
    for (int i = 0; i < 4; i++) {
        int lin = t + i * 256;
        int r = lin >> 3, c4 = (lin & 7) * 4;
        *(uint4*)&Qs_hi[r*LDW + c4] = *(const uint4*)&g_Qh[(qrow0 + r)*32 + c4];
        *(uint4*)&Qs_lo[r*LDW + c4] = *(const uint4*)&g_Ql[(qrow0 + r)*32 + c4];
    }

    float m0 = -CUDART_INF_F, m1 = -CUDART_INF_F, l0 = 0.f, l1 = 0.f;
    float o[8][4];
#pragma unroll
    for (int nt = 0; nt < 8; nt++)
#pragma unroll
        for (int j = 0; j < 4; j++) o[nt][j] = 0.f;

    for (int it = 0; it < SEQ/64; it++) {
        if (it + 1 < SEQ/64) {
            int kt1 = (it + 1) * 64;
            uint32_t stoff = (uint32_t)(((it + 1) & 1) * SSTR) * 4;
            uint32_t d0 = sbase + (F_KV + cr0*LDW + cc0) * 4 + stoff;
            uint32_t d1 = sbase + (F_KV + cr1*LDW + cc1) * 4 + stoff;
            cpa16(d0,            &g_Kh[(krow0 + kt1 + cr0)*32 + cc0]);
            cpa16(d1,            &g_Kh[(krow0 + kt1 + cr1)*32 + cc1]);
            cpa16(d0 + S_KLO*4,  &g_Kl[(krow0 + kt1 + cr0)*32 + cc0]);
            cpa16(d1 + S_KLO*4,  &g_Kl[(krow0 + kt1 + cr1)*32 + cc1]);
            cpa16(d0 + S_VHI*4,  VhT + (size_t)cr0*SEQ + kt1 + cc0*2);
            cpa16(d1 + S_VHI*4,  VhT + (size_t)cr1*SEQ + kt1 + cc1*2);
            cpa16(d0 + S_VLO*4,  VlT + (size_t)cr0*SEQ + kt1 + cc0*2);
            cpa16(d1 + S_VLO*4,  VlT + (size_t)cr1*SEQ + kt1 + cc1*2);
            asm volatile("cp.async.commit_group;");
            asm volatile("cp.async.wait_group 1;");
        } else {
            asm volatile("cp.async.wait_group 0;");
        }
        __syncthreads();

        uint32_t stoff = (uint32_t)((it & 1) * SSTR) * 4;
        uint32_t k_hi_base = k_hi_base0 + stoff;
        uint32_t k_lo_base = k_hi_base + S_KLO*4;
        uint32_t v_hi_base = v_hi_base0 + stoff;
        uint32_t v_lo_base = v_hi_base + 64*LDW*4;

        // ---- S = Q K^T (base-2 domain) ----
        float s[8][4];
#pragma unroll
        for (int nt = 0; nt < 8; nt++)
#pragma unroll
            for (int j = 0; j < 4; j++) s[nt][j] = 0.f;
#pragma unroll
        for (int ktp = 0; ktp < 2; ktp++) {
            uint32_t qh0[4], qh1[4], ql0[4], ql1[4];
            ldsm4(qh0, q_hi_base + (ktp*2+0)*32);
            ldsm4(qh1, q_hi_base + (ktp*2+1)*32);
            ldsm4(ql0, q_lo_base + (ktp*2+0)*32);
            ldsm4(ql1, q_lo_base + (ktp*2+1)*32);
#pragma unroll
            for (int nt = 0; nt < 8; nt++) {
                uint32_t kh[4], klo[4];
                uint32_t off = (uint32_t)(nt*8*LDW + ktp*16)*4;
                ldsm4(kh,  k_hi_base + off);
                ldsm4(klo, k_lo_base + off);
                mma16(s[nt], qh0, kh);
                mma16(s[nt], qh0, klo);
                mma16(s[nt], ql0, kh);
                mma16(s[nt], qh1, kh+2);
                mma16(s[nt], qh1, klo+2);
                mma16(s[nt], ql1, kh+2);
            }
        }

        // ---- online softmax (exp2) ----
        float mx0 = -CUDART_INF_F, mx1 = -CUDART_INF_F;
#pragma unroll
        for (int nt = 0; nt < 8; nt++) {
            mx0 = fmaxf(mx0, fmaxf(s[nt][0], s[nt][1]));
            mx1 = fmaxf(mx1, fmaxf(s[nt][2], s[nt][3]));
        }
        mx0 = fmaxf(mx0, __shfl_xor_sync(0xffffffffu, mx0, 1));
        mx0 = fmaxf(mx0, __shfl_xor_sync(0xffffffffu, mx0, 2));
        mx1 = fmaxf(mx1, __shfl_xor_sync(0xffffffffu, mx1, 1));
        mx1 = fmaxf(mx1, __shfl_xor_sync(0xffffffffu, mx1, 2));
        float mn0 = fmaxf(m0, mx0), mn1 = fmaxf(m1, mx1);
        float f0 = exp2f(m0 - mn0), f1 = exp2f(m1 - mn1);
        float s0 = 0.f, s1 = 0.f;
#pragma unroll
        for (int nt = 0; nt < 8; nt++) {
            s[nt][0] = exp2f(s[nt][0] - mn0); s0 += s[nt][0];
            s[nt][1] = exp2f(s[nt][1] - mn0); s0 += s[nt][1];
            s[nt][2] = exp2f(s[nt][2] - mn1); s1 += s[nt][2];
            s[nt][3] = exp2f(s[nt][3] - mn1); s1 += s[nt][3];
        }
        s0 += __shfl_xor_sync(0xffffffffu, s0, 1);
        s0 += __shfl_xor_sync(0xffffffffu, s0, 2);
        s1 += __shfl_xor_sync(0xffffffffu, s1, 1);
        s1 += __shfl_xor_sync(0xffffffffu, s1, 2);
        l0 = l0 * f0 + s0; l1 = l1 * f1 + s1;
        m0 = mn0; m1 = mn1;
#pragma unroll
        for (int nt = 0; nt < 8; nt++) {
            o[nt][0] *= f0; o[nt][1] *= f0;
            o[nt][2] *= f1; o[nt][3] *= f1;
        }

        // ---- O += P V  (P in registers) ----
#pragma unroll
        for (int kc = 0; kc < 4; kc++) {
            uint32_t ah[4], al[4];
            split2(s[2*kc][0],   s[2*kc][1],   ah[0], al[0]);
            split2(s[2*kc][2],   s[2*kc][3],   ah[1], al[1]);
            split2(s[2*kc+1][0], s[2*kc+1][1], ah[2], al[2]);
            split2(s[2*kc+1][2], s[2*kc+1][3], ah[3], al[3]);
#pragma unroll
            for (int n16 = 0; n16 < 4; n16++) {
                uint32_t vh4[4], vl4[4];
                uint32_t voff = (uint32_t)(n16*16*LDW + kc*8)*4;
                ldsm4(vh4, v_hi_base + voff);
                ldsm4(vl4, v_lo_base + voff);
                mma16(o[2*n16],   ah, vh4);
                mma16(o[2*n16],   ah, vl4);
                mma16(o[2*n16],   al, vh4);
                mma16(o[2*n16+1], ah, vh4+2);
                mma16(o[2*n16+1], ah, vl4+2);
                mma16(o[2*n16+1], al, vh4+2);
            }
        }
        __syncthreads();
    }

    float inv0 = 1.f / l0, inv1 = 1.f / l1;
    int row = q0 + wid * 16 + g;
    size_t obase = (size_t)bh * SEQ * HD;
#pragma unroll
    for (int nt = 0; nt < 8; nt++) {
        int d = nt * 8 + 2 * tg;
        *(float2*)&g_O[obase + (size_t)row * HD + d]       = make_float2(o[nt][0]*inv0, o[nt][1]*inv0);
        *(float2*)&g_O[obase + (size_t)(row + 8) * HD + d] = make_float2(o[nt][2]*inv1, o[nt][3]*inv1);
    }
}

// ---------------------------------------------------------------------------
// Kernel 4: out = (mean_h g_O) @ Wo (bf16x3). (unchanged)
// ---------------------------------------------------------------------------
#define OALD2 36
#define OBLD2 136
__global__ __launch_bounds__(256, 2) void out_kernel(const float* __restrict__ Wo,
                                                     float* __restrict__ out) {
    extern __shared__ uint32_t osm[];
    uint32_t* As_hi = osm;
    uint32_t* As_lo = osm + 128*OALD2;
    uint32_t* Bs_hi = osm + 2*128*OALD2;
    uint32_t* Bs_lo = osm + 2*128*OALD2 + 32*OBLD2;

    int t = threadIdx.x;
    int lane = t & 31, wid = t >> 5;
    int wm = wid & 3, wn = wid >> 2;
    int g = lane >> 2, tg = lane & 3;
    int l15 = lane & 15, lhi4 = (lane >> 4) << 2;
    int m0 = blockIdx.y * 128, n0 = blockIdx.x * 128;

    uint32_t a_hi_base = (uint32_t)__cvta_generic_to_shared(osm)
                       + ((wm*32 + l15)*OALD2 + lhi4) * 4;
    uint32_t a_lo_base = a_hi_base + 128*OALD2*4;

#pragma unroll
    for (int i = 0; i < 8; i++) {
        int lin = t + i * 256;
        int r = lin >> 4, c4 = (lin & 15) * 4;
        int grow = m0 + r;
        int bb = grow >> 11, ss = grow & 2047;
        float ax = 0.f, ay = 0.f, az = 0.f, aw = 0.f;
#pragma unroll
        for (int h = 0; h < KVH; h++) {
            float4 v = *(const float4*)&g_O[(((size_t)bb * KVH + h) * SEQ + ss) * HD + c4];
            ax += v.x; ay += v.y; az += v.z; aw += v.w;
        }
        int k2 = c4 >> 1;
        split2(ax*0.25f, ay*0.25f, As_hi[r*OALD2 + k2],     As_lo[r*OALD2 + k2]);
        split2(az*0.25f, aw*0.25f, As_hi[r*OALD2 + k2 + 1], As_lo[r*OALD2 + k2 + 1]);
    }
#pragma unroll
    for (int j = 0; j < 16; j++) {
        int idx = t + j * 256;
        int k2 = idx >> 7, n = idx & 127;
        float w0 = Wo[(size_t)(2*k2) * EMB + n0 + n];
        float w1 = Wo[(size_t)(2*k2 + 1) * EMB + n0 + n];
        split2(w0, w1, Bs_hi[k2*OBLD2 + n], Bs_lo[k2*OBLD2 + n]);
    }
    __syncthreads();

    float c[2][8][4];
#pragma unroll
    for (int mt = 0; mt < 2; mt++)
#pragma unroll
        for (int nt = 0; nt < 8; nt++)
#pragma unroll
            for (int j = 0; j < 4; j++) c[mt][nt][j] = 0.f;

#pragma unroll
    for (int kt = 0; kt < 4; kt++) {
        uint32_t ah[2][4], al[2][4];
#pragma unroll
        for (int mt = 0; mt < 2; mt++) {
            ldsm4(ah[mt], a_hi_base + (mt*16*OALD2 + kt*8)*4);
            ldsm4(al[mt], a_lo_base + (mt*16*OALD2 + kt*8)*4);
        }
#pragma unroll
        for (int nt = 0; nt < 8; nt++) {
            int nn = wn * 64 + nt * 8 + g;
            uint32_t bh[2], bl[2];
            bh[0] = Bs_hi[(kt*8+tg)*OBLD2 + nn];   bh[1] = Bs_hi[(kt*8+tg+4)*OBLD2 + nn];
            bl[0] = Bs_lo[(kt*8+tg)*OBLD2 + nn];   bl[1] = Bs_lo[(kt*8+tg+4)*OBLD2 + nn];
            mma16(c[0][nt], ah[0], bh);
            mma16(c[0][nt], ah[0], bl);
            mma16(c[0][nt], al[0], bh);
            mma16(c[1][nt], ah[1], bh);
            mma16(c[1][nt], ah[1], bl);
            mma16(c[1][nt], al[1], bh);
        }
    }

#pragma unroll
    for (int mt = 0; mt < 2; mt++) {
#pragma unroll
        for (int nt = 0; nt < 8; nt++) {
            int row = m0 + wm * 32 + mt * 16 + g;
            int col = n0 + wn * 64 + nt * 8 + 2 * tg;
            *(float2*)&out[(size_t)row * EMB + col]       = make_float2(c[mt][nt][0], c[mt][nt][1]);
            *(float2*)&out[(size_t)(row + 8) * EMB + col] = make_float2(c[mt][nt][2], c[mt][nt][3]);
        }
    }
}

// ---------------------------------------------------------------------------
extern "C" void kernel_launch(void* const* d_in, const int* in_sizes, int n_in,
                              void* d_out, int out_size) {
    const float* q  = (const float*)d_in[0];
    const float* kv = (const float*)d_in[1];
    const float* Wq = (const float*)d_in[2];
    const float* Wk = (const float*)d_in[3];
    const float* Wv = (const float*)d_in[4];
    const float* Wo = (const float*)d_in[5];
    float* out = (float*)d_out;

    const int proj_smem  = PROJ_SMEM_WORDS * 4;             // 55296
    const int flash_smem = FLASH_SMEM_WORDS * 4;            // 110592
    const int out_smem   = (2*128*OALD2 + 2*32*OBLD2) * 4;  // 71680
    cudaFuncSetAttribute(proj_kernel,  cudaFuncAttributeMaxDynamicSharedMemorySize, proj_smem);
    cudaFuncSetAttribute(flash_kernel, cudaFuncAttributeMaxDynamicSharedMemorySize, flash_smem);
    cudaFuncSetAttribute(out_kernel,   cudaFuncAttributeMaxDynamicSharedMemorySize, out_smem);

    prep_w_kernel<<<(3*512*NPROJ) / 256, 256>>>(Wq, Wk, Wv);
    rope_table_kernel<<<(SEQ * 32) / 256, 256>>>();
    proj_kernel<<<dim3(6, MROWS / 128), 256, proj_smem>>>(q, kv);
    flash_kernel<<<dim3(SEQ / 128, BATCH * KVH), 256, flash_smem>>>();
    out_kernel<<<dim3(EMB / 128, MROWS / 128), 256, out_smem>>>(Wo, out);
}

// round 9
// speedup vs baseline: 3.3424x; 1.0353x over previous
#include <cuda_runtime.h>
#include <cuda_bf16.h>
#include <math_constants.h>
#include <stdint.h>

#define BATCH 4
#define SEQ   2048
#define EMB   1024
#define KVH   4
#define QHN   16
#define GRP   4
#define HD    64
#define NPROJ 256
#define MROWS (BATCH*SEQ)
#define QSCALE 0.1803368801111244f   // 0.125 * log2(e)

// Pre-split storage: bf16 hi/lo planes
__device__ uint32_t g_Whi[3*512*NPROJ], g_Wlo[3*512*NPROJ];
__device__ uint32_t g_Qh[BATCH*KVH*SEQ*32], g_Ql[BATCH*KVH*SEQ*32];
__device__ uint32_t g_Kh[BATCH*KVH*SEQ*32], g_Kl[BATCH*KVH*SEQ*32];
__device__ __nv_bfloat16 g_VhT[BATCH*KVH*HD*SEQ], g_VlT[BATCH*KVH*HD*SEQ]; // [bh][d][s]
__device__ float g_O[BATCH*KVH*SEQ*HD];
__device__ float2 g_rope[SEQ * 32];

// ---- helpers ---------------------------------------------------------------
__device__ __forceinline__ uint32_t pack_bf2(float x, float y) {
    __nv_bfloat162 h = __floats2bfloat162_rn(x, y);
    return *reinterpret_cast<uint32_t*>(&h);
}
__device__ __forceinline__ void split2(float x, float y, uint32_t& hi, uint32_t& lo) {
    __nv_bfloat162 h = __floats2bfloat162_rn(x, y);
    float2 hf = __bfloat1622float2(h);
    hi = *reinterpret_cast<uint32_t*>(&h);
    lo = pack_bf2(x - hf.x, y - hf.y);
}
__device__ __forceinline__ void mma16(float c[4], const uint32_t a[4], const uint32_t b[2]) {
    asm volatile("mma.sync.aligned.m16n8k16.row.col.f32.bf16.bf16.f32 "
        "{%0,%1,%2,%3}, {%4,%5,%6,%7}, {%8,%9}, {%0,%1,%2,%3};\n"
        : "+f"(c[0]), "+f"(c[1]), "+f"(c[2]), "+f"(c[3])
        : "r"(a[0]), "r"(a[1]), "r"(a[2]), "r"(a[3]), "r"(b[0]), "r"(b[1]));
}
__device__ __forceinline__ void ldsm4(uint32_t r[4], uint32_t addr) {
    asm volatile("ldmatrix.sync.aligned.m8n8.x4.shared.b16 {%0,%1,%2,%3}, [%4];"
        : "=r"(r[0]), "=r"(r[1]), "=r"(r[2]), "=r"(r[3]) : "r"(addr) : "memory");
}
__device__ __forceinline__ void cpa16(uint32_t dst, const void* src) {
    asm volatile("cp.async.cg.shared.global [%0], [%1], 16;" :: "r"(dst), "l"(src));
}

// ---------------------------------------------------------------------------
// Kernel 0a: prep W.  0b: RoPE table.
// ---------------------------------------------------------------------------
__global__ void prep_w_kernel(const float* __restrict__ Wq,
                              const float* __restrict__ Wk,
                              const float* __restrict__ Wv) {
    int i = blockIdx.x * blockDim.x + threadIdx.x;
    int mat = i >> 17;
    int rem = i & 131071;
    int k2 = rem >> 8, n = rem & 255;
    float w0, w1;
    if (mat == 0) {
        int h = n >> 6, d = n & 63;
        w0 = 0.f; w1 = 0.f;
#pragma unroll
        for (int g = 0; g < GRP; g++) {
            w0 += Wq[(size_t)(2*k2)   * (QHN*HD) + (h*GRP + g)*HD + d];
            w1 += Wq[(size_t)(2*k2+1) * (QHN*HD) + (h*GRP + g)*HD + d];
        }
    } else {
        const float* W = (mat == 1) ? Wk : Wv;
        w0 = W[(size_t)(2*k2)   * NPROJ + n];
        w1 = W[(size_t)(2*k2+1) * NPROJ + n];
    }
    split2(w0, w1, g_Whi[i], g_Wlo[i]);
}
__global__ void rope_table_kernel() {
    int i = blockIdx.x * blockDim.x + threadIdx.x;
    int s = i >> 5, d2 = i & 31;
    float freq = powf(10000.0f, -(float)(2*d2) * (1.0f/64.0f));
    float sn, cs; sincosf((float)s * freq, &sn, &cs);
    g_rope[i] = make_float2(cs, sn);
}

// ---------------------------------------------------------------------------
// Kernel 2: QKV projection (bf16x3) + RoPE + pre-split epilogue. (unchanged)
// ---------------------------------------------------------------------------
#define ALD2 20
#define BLD2 136
#define P_ALO (128*ALD2)
#define P_BHI (2*128*ALD2)
#define BSTG  (2*16*BLD2)
#define BLO_OFF (16*BLD2)
#define PROJ_SMEM_WORDS (P_BHI + 2*BSTG)
__global__ __launch_bounds__(256, 2) void proj_kernel(const float* __restrict__ q,
                                                      const float* __restrict__ kv) {
    extern __shared__ uint32_t psm[];
    uint32_t* As_hi = psm;
    uint32_t* As_lo = psm + P_ALO;

    int bx = blockIdx.x;
    int mat   = bx >> 1;
    int ncol0 = (bx & 1) * 128;
    int m0    = blockIdx.y * 128;

    const float* A = (mat == 0) ? q : kv;
    int matbase = mat << 17;

    int t = threadIdx.x;
    int lane = t & 31, wid = t >> 5;
    int wm = wid & 3, wn = wid >> 2;
    int g = lane >> 2, tg = lane & 3;
    int l15 = lane & 15, lhi4 = (lane >> 4) << 2;

    uint32_t sbase = (uint32_t)__cvta_generic_to_shared(psm);
    uint32_t a_hi_base = sbase + ((wm*32 + l15)*ALD2 + lhi4) * 4;
    uint32_t a_lo_base = a_hi_base + P_ALO*4;

    float c[2][8][4];
#pragma unroll
    for (int mt = 0; mt < 2; mt++)
#pragma unroll
        for (int nt = 0; nt < 8; nt++)
#pragma unroll
            for (int j = 0; j < 4; j++) c[mt][nt][j] = 0.f;

    float4 av[4];
#pragma unroll
    for (int i = 0; i < 4; i++) {
        int lin = t + i * 256;
        av[i] = *(const float4*)&A[(size_t)(m0 + (lin >> 3)) * EMB + (lin & 7) * 4];
    }
#pragma unroll
    for (int j = 0; j < 2; j++) {
        int idx = t + j * 256;
        int k2 = idx >> 5, n4 = (idx & 31) * 4;
        int gidx = matbase + k2 * NPROJ + ncol0 + n4;
        cpa16(sbase + (P_BHI + k2*BLD2 + n4) * 4,           &g_Whi[gidx]);
        cpa16(sbase + (P_BHI + BLO_OFF + k2*BLD2 + n4) * 4, &g_Wlo[gidx]);
    }
    asm volatile("cp.async.commit_group;");

    for (int k0 = 0; k0 < EMB; k0 += 32) {
        if (k0) __syncthreads();
#pragma unroll
        for (int i = 0; i < 4; i++) {
            int lin = t + i * 256;
            int r = lin >> 3, c4 = (lin & 7) * 4;
            int k2 = c4 >> 1;
            split2(av[i].x, av[i].y, As_hi[r*ALD2 + k2],     As_lo[r*ALD2 + k2]);
            split2(av[i].z, av[i].w, As_hi[r*ALD2 + k2 + 1], As_lo[r*ALD2 + k2 + 1]);
        }
        if (k0 + 32 < EMB) {
#pragma unroll
            for (int i = 0; i < 4; i++) {
                int lin = t + i * 256;
                av[i] = *(const float4*)&A[(size_t)(m0 + (lin >> 3)) * EMB + k0 + 32 + (lin & 7) * 4];
            }
            uint32_t bst = P_BHI + ((((k0 >> 5) + 1) & 1) ? BSTG : 0);
#pragma unroll
            for (int j = 0; j < 2; j++) {
                int idx = t + j * 256;
                int k2 = idx >> 5, n4 = (idx & 31) * 4;
                int gidx = matbase + (((k0 + 32) >> 1) + k2) * NPROJ + ncol0 + n4;
                cpa16(sbase + (bst + k2*BLD2 + n4) * 4,           &g_Whi[gidx]);
                cpa16(sbase + (bst + BLO_OFF + k2*BLD2 + n4) * 4, &g_Wlo[gidx]);
            }
            asm volatile("cp.async.commit_group;");
            asm volatile("cp.async.wait_group 1;");
        } else {
            asm volatile("cp.async.wait_group 0;");
        }
        __syncthreads();

        uint32_t* Bs_hi = psm + P_BHI + (((k0 >> 5) & 1) ? BSTG : 0);
        uint32_t* Bs_lo = Bs_hi + BLO_OFF;
#pragma unroll
        for (int kt = 0; kt < 2; kt++) {
            uint32_t ah[2][4], al[2][4];
#pragma unroll
            for (int mt = 0; mt < 2; mt++) {
                ldsm4(ah[mt], a_hi_base + (mt*16*ALD2 + kt*8)*4);
                ldsm4(al[mt], a_lo_base + (mt*16*ALD2 + kt*8)*4);
            }
#pragma unroll
            for (int nt = 0; nt < 8; nt++) {
                int nn = wn * 64 + nt * 8 + g;
                uint32_t bh[2], bl[2];
                bh[0] = Bs_hi[(kt*8+tg)*BLD2 + nn];   bh[1] = Bs_hi[(kt*8+tg+4)*BLD2 + nn];
                bl[0] = Bs_lo[(kt*8+tg)*BLD2 + nn];   bl[1] = Bs_lo[(kt*8+tg+4)*BLD2 + nn];
                mma16(c[0][nt], ah[0], bh);
                mma16(c[0][nt], ah[0], bl);
                mma16(c[0][nt], al[0], bh);
                mma16(c[1][nt], ah[1], bh);
                mma16(c[1][nt], ah[1], bl);
                mma16(c[1][nt], al[1], bh);
            }
        }
    }

#pragma unroll
    for (int mt = 0; mt < 2; mt++) {
#pragma unroll
        for (int nt = 0; nt < 8; nt++) {
            int row  = m0 + wm * 32 + mt * 16 + g;
            int ncol = ncol0 + wn * 64 + nt * 8 + 2 * tg;
            int h = ncol >> 6, d = ncol & 63;
#pragma unroll
            for (int rr = 0; rr < 2; rr++) {
                int r2 = row + rr * 8;
                int bb = r2 >> 11, ss = r2 & 2047;
                float x1 = c[mt][nt][rr*2+0];
                float x2 = c[mt][nt][rr*2+1];
                int bh_ = bb * KVH + h;
                if (mat < 2) {
                    float2 cssn = g_rope[ss * 32 + (d >> 1)];
                    float y1 = x1*cssn.x - x2*cssn.y;
                    float y2 = x1*cssn.y + x2*cssn.x;
                    size_t idx = ((size_t)bh_ * SEQ + ss) * 32 + (d >> 1);
                    if (mat == 0) {
                        split2(y1 * QSCALE, y2 * QSCALE, g_Qh[idx], g_Ql[idx]);
                    } else {
                        split2(y1, y2, g_Kh[idx], g_Kl[idx]);
                    }
                } else {
                    size_t vb = ((size_t)bh_ * HD + d) * SEQ + ss;
                    __nv_bfloat16 h1 = __float2bfloat16_rn(x1);
                    __nv_bfloat16 h2 = __float2bfloat16_rn(x2);
                    g_VhT[vb]       = h1;
                    g_VhT[vb + SEQ] = h2;
                    g_VlT[vb]       = __float2bfloat16_rn(x1 - __bfloat162float(h1));
                    g_VlT[vb + SEQ] = __float2bfloat16_rn(x2 - __bfloat162float(h2));
                }
            }
        }
    }
}

// ---------------------------------------------------------------------------
// Kernel 3: flash attention v2. 4 warps x 32 Q rows (M=32 warp tile):
// halves ldsm-per-MMA. Reg-resident P, cp.async double-buffered K/V, exp2.
// ---------------------------------------------------------------------------
#define LDW 36
#define F_QLO (128*LDW)
#define F_KV  (2*128*LDW)
#define SSTR  (4*64*LDW)
#define S_KLO (64*LDW)
#define S_VHI (2*64*LDW)
#define S_VLO (3*64*LDW)
#define FLASH_SMEM_WORDS (F_KV + 2*SSTR)   // 27648 words = 110592 B
__global__ __launch_bounds__(128, 2) void flash_kernel() {
    extern __shared__ uint32_t sm[];
    uint32_t* Qs_hi = sm;
    uint32_t* Qs_lo = sm + F_QLO;

    int t = threadIdx.x;
    int lane = t & 31, wid = t >> 5;   // 4 warps
    int g = lane >> 2, tg = lane & 3;
    int l15 = lane & 15, lhi4 = (lane >> 4) << 2, l7 = lane & 7;
    int bh = blockIdx.y;
    int q0 = blockIdx.x * 128;
    size_t qrow0 = (size_t)bh * SEQ + q0;
    size_t krow0 = (size_t)bh * SEQ;

    uint32_t sbase = (uint32_t)__cvta_generic_to_shared(sm);
    uint32_t q_hi_base = sbase + ((wid*32 + l15)*LDW + lhi4) * 4;
    uint32_t q_lo_base = q_hi_base + F_QLO*4;
    uint32_t k_hi_base0 = sbase + (F_KV + l7*LDW + ((lane>>3)&1)*4 + (lane>>4)*8) * 4;
    uint32_t v_hi_base0 = sbase + (F_KV + S_VHI + (l7 + (lane>>4)*8)*LDW + ((lane>>3)&1)*4) * 4;

    const __nv_bfloat16* VhT = g_VhT + (size_t)bh * HD * SEQ;
    const __nv_bfloat16* VlT = g_VlT + (size_t)bh * HD * SEQ;

    // cp.async coords: 4 quads per plane per thread (128 threads, 512 quads/plane)
    int cr[4], cc[4];
#pragma unroll
    for (int i = 0; i < 4; i++) {
        int lin = t + i * 128;
        cr[i] = lin >> 3; cc[i] = (lin & 7) * 4;
    }

    // ---- prologue: stage 0 loads + Q staging ----
#pragma unroll
    for (int i = 0; i < 4; i++) {
        uint32_t d = sbase + (F_KV + cr[i]*LDW + cc[i]) * 4;
        cpa16(d,            &g_Kh[(krow0 + cr[i])*32 + cc[i]]);
        cpa16(d + S_KLO*4,  &g_Kl[(krow0 + cr[i])*32 + cc[i]]);
        cpa16(d + S_VHI*4,  VhT + (size_t)cr[i]*SEQ + cc[i]*2);
        cpa16(d + S_VLO*4,  VlT + (size_t)cr[i]*SEQ + cc[i]*2);
    }
    asm volatile("cp.async.commit_group;");
#pragma unroll
    for (int i = 0; i < 8; i++) {
        int lin = t + i * 128;
        int r = lin >> 3, c4 = (lin & 7) * 4;
        *(uint4*)&Qs_hi[r*LDW + c4] = *(const uint4*)&g_Qh[(qrow0 + r)*32 + c4];
        *(uint4*)&Qs_lo[r*LDW + c4] = *(const uint4*)&g_Ql[(qrow0 + r)*32 + c4];
    }

    float mrow[2][2], lrow[2][2];
#pragma unroll
    for (int mt = 0; mt < 2; mt++) { mrow[mt][0] = mrow[mt][1] = -CUDART_INF_F; lrow[mt][0] = lrow[mt][1] = 0.f; }
    float o[2][8][4];
#pragma unroll
    for (int mt = 0; mt < 2; mt++)
#pragma unroll
        for (int nt = 0; nt < 8; nt++)
#pragma unroll
            for (int j = 0; j < 4; j++) o[mt][nt][j] = 0.f;

    for (int it = 0; it < SEQ/64; it++) {
        if (it + 1 < SEQ/64) {
            int kt1 = (it + 1) * 64;
            uint32_t stoff = (uint32_t)(((it + 1) & 1) * SSTR) * 4;
#pragma unroll
            for (int i = 0; i < 4; i++) {
                uint32_t d = sbase + (F_KV + cr[i]*LDW + cc[i]) * 4 + stoff;
                cpa16(d,            &g_Kh[(krow0 + kt1 + cr[i])*32 + cc[i]]);
                cpa16(d + S_KLO*4,  &g_Kl[(krow0 + kt1 + cr[i])*32 + cc[i]]);
                cpa16(d + S_VHI*4,  VhT + (size_t)cr[i]*SEQ + kt1 + cc[i]*2);
                cpa16(d + S_VLO*4,  VlT + (size_t)cr[i]*SEQ + kt1 + cc[i]*2);
            }
            asm volatile("cp.async.commit_group;");
            asm volatile("cp.async.wait_group 1;");
        } else {
            asm volatile("cp.async.wait_group 0;");
        }
        __syncthreads();

        uint32_t stoff = (uint32_t)((it & 1) * SSTR) * 4;
        uint32_t k_hi_base = k_hi_base0 + stoff;
        uint32_t k_lo_base = k_hi_base + S_KLO*4;
        uint32_t v_hi_base = v_hi_base0 + stoff;
        uint32_t v_lo_base = v_hi_base + 64*LDW*4;

        // ---- S = Q K^T (base-2 domain) ----
        float s[2][8][4];
#pragma unroll
        for (int mt = 0; mt < 2; mt++)
#pragma unroll
            for (int nt = 0; nt < 8; nt++)
#pragma unroll
                for (int j = 0; j < 4; j++) s[mt][nt][j] = 0.f;
#pragma unroll
        for (int ktp = 0; ktp < 2; ktp++) {
            uint32_t qh[2][2][4], ql[2][2][4];
#pragma unroll
            for (int mt = 0; mt < 2; mt++) {
                uint32_t moff = (uint32_t)(mt*16*LDW)*4;
                ldsm4(qh[mt][0], q_hi_base + moff + (ktp*2+0)*32);
                ldsm4(qh[mt][1], q_hi_base + moff + (ktp*2+1)*32);
                ldsm4(ql[mt][0], q_lo_base + moff + (ktp*2+0)*32);
                ldsm4(ql[mt][1], q_lo_base + moff + (ktp*2+1)*32);
            }
#pragma unroll
            for (int nt = 0; nt < 8; nt++) {
                uint32_t kh[4], klo[4];
                uint32_t off = (uint32_t)(nt*8*LDW + ktp*16)*4;
                ldsm4(kh,  k_hi_base + off);
                ldsm4(klo, k_lo_base + off);
#pragma unroll
                for (int mt = 0; mt < 2; mt++) {
                    mma16(s[mt][nt], qh[mt][0], kh);
                    mma16(s[mt][nt], qh[mt][0], klo);
                    mma16(s[mt][nt], ql[mt][0], kh);
                    mma16(s[mt][nt], qh[mt][1], kh+2);
                    mma16(s[mt][nt], qh[mt][1], klo+2);
                    mma16(s[mt][nt], ql[mt][1], kh+2);
                }
            }
        }

        // ---- online softmax (exp2), per m-tile ----
#pragma unroll
        for (int mt = 0; mt < 2; mt++) {
            float mx0 = -CUDART_INF_F, mx1 = -CUDART_INF_F;
#pragma unroll
            for (int nt = 0; nt < 8; nt++) {
                mx0 = fmaxf(mx0, fmaxf(s[mt][nt][0], s[mt][nt][1]));
                mx1 = fmaxf(mx1, fmaxf(s[mt][nt][2], s[mt][nt][3]));
            }
            mx0 = fmaxf(mx0, __shfl_xor_sync(0xffffffffu, mx0, 1));
            mx0 = fmaxf(mx0, __shfl_xor_sync(0xffffffffu, mx0, 2));
            mx1 = fmaxf(mx1, __shfl_xor_sync(0xffffffffu, mx1, 1));
            mx1 = fmaxf(mx1, __shfl_xor_sync(0xffffffffu, mx1, 2));
            float mn0 = fmaxf(mrow[mt][0], mx0), mn1 = fmaxf(mrow[mt][1], mx1);
            float f0 = exp2f(mrow[mt][0] - mn0), f1 = exp2f(mrow[mt][1] - mn1);
            float s0 = 0.f, s1 = 0.f;
#pragma unroll
            for (int nt = 0; nt < 8; nt++) {
                s[mt][nt][0] = exp2f(s[mt][nt][0] - mn0); s0 += s[mt][nt][0];
                s[mt][nt][1] = exp2f(s[mt][nt][1] - mn0); s0 += s[mt][nt][1];
                s[mt][nt][2] = exp2f(s[mt][nt][2] - mn1); s1 += s[mt][nt][2];
                s[mt][nt][3] = exp2f(s[mt][nt][3] - mn1); s1 += s[mt][nt][3];
            }
            s0 += __shfl_xor_sync(0xffffffffu, s0, 1);
            s0 += __shfl_xor_sync(0xffffffffu, s0, 2);
            s1 += __shfl_xor_sync(0xffffffffu, s1, 1);
            s1 += __shfl_xor_sync(0xffffffffu, s1, 2);
            lrow[mt][0] = lrow[mt][0] * f0 + s0; lrow[mt][1] = lrow[mt][1] * f1 + s1;
            mrow[mt][0] = mn0; mrow[mt][1] = mn1;
#pragma unroll
            for (int nt = 0; nt < 8; nt++) {
                o[mt][nt][0] *= f0; o[mt][nt][1] *= f0;
                o[mt][nt][2] *= f1; o[mt][nt][3] *= f1;
            }
        }

        // ---- O += P V  (P in registers via C->A fragment identity) ----
#pragma unroll
        for (int kc = 0; kc < 4; kc++) {
            uint32_t ah[2][4], al[2][4];
#pragma unroll
            for (int mt = 0; mt < 2; mt++) {
                split2(s[mt][2*kc][0],   s[mt][2*kc][1],   ah[mt][0], al[mt][0]);
                split2(s[mt][2*kc][2],   s[mt][2*kc][3],   ah[mt][1], al[mt][1]);
                split2(s[mt][2*kc+1][0], s[mt][2*kc+1][1], ah[mt][2], al[mt][2]);
                split2(s[mt][2*kc+1][2], s[mt][2*kc+1][3], ah[mt][3], al[mt][3]);
            }
#pragma unroll
            for (int n16 = 0; n16 < 4; n16++) {
                uint32_t vh4[4], vl4[4];
                uint32_t voff = (uint32_t)(n16*16*LDW + kc*8)*4;
                ldsm4(vh4, v_hi_base + voff);
                ldsm4(vl4, v_lo_base + voff);
#pragma unroll
                for (int mt = 0; mt < 2; mt++) {
                    mma16(o[mt][2*n16],   ah[mt], vh4);
                    mma16(o[mt][2*n16],   ah[mt], vl4);
                    mma16(o[mt][2*n16],   al[mt], vh4);
                    mma16(o[mt][2*n16+1], ah[mt], vh4+2);
                    mma16(o[mt][2*n16+1], ah[mt], vl4+2);
                    mma16(o[mt][2*n16+1], al[mt], vh4+2);
                }
            }
        }
        __syncthreads();
    }

    size_t obase = (size_t)bh * SEQ * HD;
#pragma unroll
    for (int mt = 0; mt < 2; mt++) {
        float inv0 = 1.f / lrow[mt][0], inv1 = 1.f / lrow[mt][1];
        int row = q0 + wid * 32 + mt * 16 + g;
#pragma unroll
        for (int nt = 0; nt < 8; nt++) {
            int d = nt * 8 + 2 * tg;
            *(float2*)&g_O[obase + (size_t)row * HD + d]       = make_float2(o[mt][nt][0]*inv0, o[mt][nt][1]*inv0);
            *(float2*)&g_O[obase + (size_t)(row + 8) * HD + d] = make_float2(o[mt][nt][2]*inv1, o[mt][nt][3]*inv1);
        }
    }
}

// ---------------------------------------------------------------------------
// Kernel 4: out = (mean_h g_O) @ Wo (bf16x3). (unchanged)
// ---------------------------------------------------------------------------
#define OALD2 36
#define OBLD2 136
__global__ __launch_bounds__(256, 2) void out_kernel(const float* __restrict__ Wo,
                                                     float* __restrict__ out) {
    extern __shared__ uint32_t osm[];
    uint32_t* As_hi = osm;
    uint32_t* As_lo = osm + 128*OALD2;
    uint32_t* Bs_hi = osm + 2*128*OALD2;
    uint32_t* Bs_lo = osm + 2*128*OALD2 + 32*OBLD2;

    int t = threadIdx.x;
    int lane = t & 31, wid = t >> 5;
    int wm = wid & 3, wn = wid >> 2;
    int g = lane >> 2, tg = lane & 3;
    int l15 = lane & 15, lhi4 = (lane >> 4) << 2;
    int m0 = blockIdx.y * 128, n0 = blockIdx.x * 128;

    uint32_t a_hi_base = (uint32_t)__cvta_generic_to_shared(osm)
                       + ((wm*32 + l15)*OALD2 + lhi4) * 4;
    uint32_t a_lo_base = a_hi_base + 128*OALD2*4;

#pragma unroll
    for (int i = 0; i < 8; i++) {
        int lin = t + i * 256;
        int r = lin >> 4, c4 = (lin & 15) * 4;
        int grow = m0 + r;
        int bb = grow >> 11, ss = grow & 2047;
        float ax = 0.f, ay = 0.f, az = 0.f, aw = 0.f;
#pragma unroll
        for (int h = 0; h < KVH; h++) {
            float4 v = *(const float4*)&g_O[(((size_t)bb * KVH + h) * SEQ + ss) * HD + c4];
            ax += v.x; ay += v.y; az += v.z; aw += v.w;
        }
        int k2 = c4 >> 1;
        split2(ax*0.25f, ay*0.25f, As_hi[r*OALD2 + k2],     As_lo[r*OALD2 + k2]);
        split2(az*0.25f, aw*0.25f, As_hi[r*OALD2 + k2 + 1], As_lo[r*OALD2 + k2 + 1]);
    }
#pragma unroll
    for (int j = 0; j < 16; j++) {
        int idx = t + j * 256;
        int k2 = idx >> 7, n = idx & 127;
        float w0 = Wo[(size_t)(2*k2) * EMB + n0 + n];
        float w1 = Wo[(size_t)(2*k2 + 1) * EMB + n0 + n];
        split2(w0, w1, Bs_hi[k2*OBLD2 + n], Bs_lo[k2*OBLD2 + n]);
    }
    __syncthreads();

    float c[2][8][4];
#pragma unroll
    for (int mt = 0; mt < 2; mt++)
#pragma unroll
        for (int nt = 0; nt < 8; nt++)
#pragma unroll
            for (int j = 0; j < 4; j++) c[mt][nt][j] = 0.f;

#pragma unroll
    for (int kt = 0; kt < 4; kt++) {
        uint32_t ah[2][4], al[2][4];
#pragma unroll
        for (int mt = 0; mt < 2; mt++) {
            ldsm4(ah[mt], a_hi_base + (mt*16*OALD2 + kt*8)*4);
            ldsm4(al[mt], a_lo_base + (mt*16*OALD2 + kt*8)*4);
        }
#pragma unroll
        for (int nt = 0; nt < 8; nt++) {
            int nn = wn * 64 + nt * 8 + g;
            uint32_t bh[2], bl[2];
            bh[0] = Bs_hi[(kt*8+tg)*OBLD2 + nn];   bh[1] = Bs_hi[(kt*8+tg+4)*OBLD2 + nn];
            bl[0] = Bs_lo[(kt*8+tg)*OBLD2 + nn];   bl[1] = Bs_lo[(kt*8+tg+4)*OBLD2 + nn];
            mma16(c[0][nt], ah[0], bh);
            mma16(c[0][nt], ah[0], bl);
            mma16(c[0][nt], al[0], bh);
            mma16(c[1][nt], ah[1], bh);
            mma16(c[1][nt], ah[1], bl);
            mma16(c[1][nt], al[1], bh);
        }
    }

#pragma unroll
    for (int mt = 0; mt < 2; mt++) {
#pragma unroll
        for (int nt = 0; nt < 8; nt++) {
            int row = m0 + wm * 32 + mt * 16 + g;
            int col = n0 + wn * 64 + nt * 8 + 2 * tg;
            *(float2*)&out[(size_t)row * EMB + col]       = make_float2(c[mt][nt][0], c[mt][nt][1]);
            *(float2*)&out[(size_t)(row + 8) * EMB + col] = make_float2(c[mt][nt][2], c[mt][nt][3]);
        }
    }
}

// ---------------------------------------------------------------------------
extern "C" void kernel_launch(void* const* d_in, const int* in_sizes, int n_in,
                              void* d_out, int out_size) {
    const float* q  = (const float*)d_in[0];
    const float* kv = (const float*)d_in[1];
    const float* Wq = (const float*)d_in[2];
    const float* Wk = (const float*)d_in[3];
    const float* Wv = (const float*)d_in[4];
    const float* Wo = (const float*)d_in[5];
    float* out = (float*)d_out;

    const int proj_smem  = PROJ_SMEM_WORDS * 4;             // 55296
    const int flash_smem = FLASH_SMEM_WORDS * 4;            // 110592
    const int out_smem   = (2*128*OALD2 + 2*32*OBLD2) * 4;  // 71680
    cudaFuncSetAttribute(proj_kernel,  cudaFuncAttributeMaxDynamicSharedMemorySize, proj_smem);
    cudaFuncSetAttribute(flash_kernel, cudaFuncAttributeMaxDynamicSharedMemorySize, flash_smem);
    cudaFuncSetAttribute(out_kernel,   cudaFuncAttributeMaxDynamicSharedMemorySize, out_smem);

    prep_w_kernel<<<(3*512*NPROJ) / 256, 256>>>(Wq, Wk, Wv);
    rope_table_kernel<<<(SEQ * 32) / 256, 256>>>();
    proj_kernel<<<dim3(6, MROWS / 128), 256, proj_smem>>>(q, kv);
    flash_kernel<<<dim3(SEQ / 128, BATCH * KVH), 128, flash_smem>>>();
    out_kernel<<<dim3(EMB / 128, MROWS / 128), 256, out_smem>>>(Wo, out);
}